// round 10
// baseline (speedup 1.0000x reference)
#include <cuda_runtime.h>
#include <cuda_fp16.h>
#include <math.h>

#define NMAX 50000
#define EMAX 800000
#define ALPHA 0.01f

// ---- static scratch (no allocations allowed) ----
__device__ __half2 g_H1h[(size_t)NMAX * 128]; // layer-1 features fp16, head-major (256 halves/row)
__device__ __half2 g_H2h[(size_t)NMAX * 32];  // layer-2 features fp16 (64 halves/row)
__device__ __half2 g_hcat16[(size_t)NMAX * 128]; // elu(attn out) fp16, layer-2 input
__device__ float g_s1h[NMAX * 4];
__device__ float g_s2h[NMAX * 4];
__device__ float g_s1o[NMAX];
__device__ float g_s2o[NMAX];
__device__ int   g_count[NMAX];               // .bss zero-init; scan_p1 re-zeroes each call
__device__ int   g_rowptr[NMAX + 1];
__device__ int   g_cursor[NMAX];
__device__ int   g_col[EMAX];
__device__ int   g_bsum[64];

// ---------------------------------------------------------------
__device__ __forceinline__ int block_probe_is64(const int* __restrict__ w, int E)
{
    int t = threadIdx.x;
    int nElem = (E < 128) ? E : 128;
    int ok = 1;
    if (t < nElem) ok = (w[2 * t + 1] == 0);
    return __syncthreads_and(ok);
}

__device__ __forceinline__ int load_idx(const int* __restrict__ w, int pos, int is64)
{
    return is64 ? w[2 * pos] : w[pos];
}

// ---------------------------------------------------------------
// fp16 tensor-core GEMM (m16n8k16, fp32 accum), 256x64 block,
// warp tile 32x64. B converted fp32->fp16 + transposed during staging.
// Fused epilogue: fp16 mirror + score dots.
// layer 0: A = A32 (x, fp32), B = W32 + head*8192 ([k=128][n=64])
// layer 1: A = g_hcat16 (fp16), B = W32 ([k=256][n=64])
// ---------------------------------------------------------------
__device__ __forceinline__ void mma16816(
    float* d, unsigned a0, unsigned a1, unsigned a2, unsigned a3,
    unsigned b0, unsigned b1)
{
    asm volatile(
        "mma.sync.aligned.m16n8k16.row.col.f32.f16.f16.f32 "
        "{%0,%1,%2,%3}, {%4,%5,%6,%7}, {%8,%9}, {%0,%1,%2,%3};\n"
        : "+f"(d[0]), "+f"(d[1]), "+f"(d[2]), "+f"(d[3])
        : "r"(a0), "r"(a1), "r"(a2), "r"(a3), "r"(b0), "r"(b1));
}

#define ROWW 68                                  // smem words per row (136 halves)
#define GEMM_SMEM ((64 * ROWW + 256 * ROWW) * 4) // B + A = 87040 B

__global__ __launch_bounds__(256, 2) void h16_gemm(
    const float* __restrict__ A32, int lda,
    const float* __restrict__ W32,
    const float* __restrict__ attn, int layer, int M, int K)
{
    extern __shared__ unsigned dsm[];
    unsigned* Bs = dsm;                    // [64][ROWW]
    unsigned* As = dsm + 64 * ROWW;        // [256][ROWW]

    int head = blockIdx.y;
    const float* Bsrc = (layer == 0) ? W32 + (size_t)head * 8192 : W32;
    const unsigned* A16 = (const unsigned*)g_hcat16;      // used when A32==null
    const int ldaW = 128;

    int row0 = blockIdx.x * 256;

    int tid = threadIdx.x;
    int lane = tid & 31, w = tid >> 5;
    int gid = lane >> 2, tig = lane & 3;

    float acc0[8][4], acc1[8][4];
#pragma unroll
    for (int i = 0; i < 8; i++)
#pragma unroll
        for (int j = 0; j < 4; j++) { acc0[i][j] = 0.f; acc1[i][j] = 0.f; }

    for (int kc = 0; kc < K; kc += 128) {
        if (kc) __syncthreads();
        // stage B chunk [64 n][128 k]: transpose + cvt from fp32 [k][64 n]
#pragma unroll
        for (int i = 0; i < 32; i++) {
            int u = tid + i * 256;         // 0..8191
            int k = u >> 6, n = u & 63;
            __half hv = __float2half_rn(Bsrc[(size_t)(kc + k) * 64 + n]);
            ((__half*)Bs)[n * (ROWW * 2) + k] = hv;
        }
        // stage A chunk: 256 rows x 64 words
        if (A32) {
#pragma unroll
            for (int i = 0; i < 32; i++) {
                int u = tid + i * 256;
                int row = u >> 5, c4 = u & 31;
                float4 av = make_float4(0.f, 0.f, 0.f, 0.f);
                if (row0 + row < M)
                    av = *(const float4*)(A32 + (size_t)(row0 + row) * lda + kc + c4 * 4);
                __half2 lo = __floats2half2_rn(av.x, av.y);
                __half2 hi = __floats2half2_rn(av.z, av.w);
                *(uint2*)&As[row * ROWW + 2 * c4] =
                    make_uint2(*(unsigned*)&lo, *(unsigned*)&hi);
            }
        } else {
#pragma unroll
            for (int i = 0; i < 32; i++) {
                int u = tid + i * 256;
                int row = u >> 5, w2 = u & 31;
                uint2 v = make_uint2(0u, 0u);
                if (row0 + row < M)
                    v = *(const uint2*)(A16 + (size_t)(row0 + row) * ldaW + (kc >> 1) + 2 * w2);
                *(uint2*)&As[row * ROWW + 2 * w2] = v;
            }
        }
        __syncthreads();

#pragma unroll
        for (int s = 0; s < 8; s++) {          // 8 k16 steps per 128-half chunk
            int ws = s * 8;
            int rA = (w * 32 + gid) * ROWW;
            unsigned a00 = As[rA + ws + tig];
            unsigned a01 = As[rA + 8 * ROWW + ws + tig];
            unsigned a02 = As[rA + ws + 4 + tig];
            unsigned a03 = As[rA + 8 * ROWW + ws + 4 + tig];
            unsigned a10 = As[rA + 16 * ROWW + ws + tig];
            unsigned a11 = As[rA + 24 * ROWW + ws + tig];
            unsigned a12 = As[rA + 16 * ROWW + ws + 4 + tig];
            unsigned a13 = As[rA + 24 * ROWW + ws + 4 + tig];
#pragma unroll
            for (int n0 = 0; n0 < 8; n0++) {
                int rB = (n0 * 8 + gid) * ROWW + ws + tig;
                unsigned b0 = Bs[rB];
                unsigned b1 = Bs[rB + 4];
                mma16816(acc0[n0], a00, a01, a02, a03, b0, b1);
                mma16816(acc1[n0], a10, a11, a12, a13, b0, b1);
            }
        }
    }

    // ---- fused epilogue ----
    __half2* Hh2;
    int ldH2, colBase2, sStride, sOff;
    float *s1g, *s2g;
    const float* a1;
    if (layer == 0) {
        Hh2 = g_H1h; ldH2 = 128; colBase2 = head * 32;
        sStride = 4; sOff = head; s1g = g_s1h; s2g = g_s2h;
        a1 = attn + head * 128;
    } else {
        Hh2 = g_H2h; ldH2 = 32; colBase2 = 0;
        sStride = 1; sOff = 0; s1g = g_s1o; s2g = g_s2o;
        a1 = attn;
    }
    const float* a2v = a1 + 64;

    int rb = row0 + w * 32 + gid;
    int rows[4] = {rb, rb + 8, rb + 16, rb + 24};

    float d1[4] = {0.f, 0.f, 0.f, 0.f};
    float d2[4] = {0.f, 0.f, 0.f, 0.f};
#pragma unroll
    for (int n0 = 0; n0 < 8; n0++) {
        int c0 = n0 * 8 + 2 * tig;
        float w10 = __ldg(a1 + c0), w11 = __ldg(a1 + c0 + 1);
        float w20 = __ldg(a2v + c0), w21 = __ldg(a2v + c0 + 1);
        d1[0] += acc0[n0][0] * w10 + acc0[n0][1] * w11;
        d2[0] += acc0[n0][0] * w20 + acc0[n0][1] * w21;
        d1[1] += acc0[n0][2] * w10 + acc0[n0][3] * w11;
        d2[1] += acc0[n0][2] * w20 + acc0[n0][3] * w21;
        d1[2] += acc1[n0][0] * w10 + acc1[n0][1] * w11;
        d2[2] += acc1[n0][0] * w20 + acc1[n0][1] * w21;
        d1[3] += acc1[n0][2] * w10 + acc1[n0][3] * w11;
        d2[3] += acc1[n0][2] * w20 + acc1[n0][3] * w21;
    }
#pragma unroll
    for (int f = 0; f < 4; f++) {
#pragma unroll
        for (int off = 1; off < 4; off <<= 1) {
            d1[f] += __shfl_xor_sync(0xffffffffu, d1[f], off);
            d2[f] += __shfl_xor_sync(0xffffffffu, d2[f], off);
        }
    }
    if (tig == 0) {
#pragma unroll
        for (int f = 0; f < 4; f++) {
            if (rows[f] < M) {
                s1g[rows[f] * sStride + sOff] = d1[f];
                s2g[rows[f] * sStride + sOff] = d2[f];
            }
        }
    }

#pragma unroll
    for (int n0 = 0; n0 < 8; n0++) {
        int cc = colBase2 + n0 * 4 + tig;
        if (rows[0] < M)
            Hh2[(size_t)rows[0] * ldH2 + cc] = __floats2half2_rn(acc0[n0][0], acc0[n0][1]);
        if (rows[1] < M)
            Hh2[(size_t)rows[1] * ldH2 + cc] = __floats2half2_rn(acc0[n0][2], acc0[n0][3]);
        if (rows[2] < M)
            Hh2[(size_t)rows[2] * ldH2 + cc] = __floats2half2_rn(acc1[n0][0], acc1[n0][1]);
        if (rows[3] < M)
            Hh2[(size_t)rows[3] * ldH2 + cc] = __floats2half2_rn(acc1[n0][2], acc1[n0][3]);
    }
}

// ---------------------------------------------------------------
// CSR build
// ---------------------------------------------------------------
__global__ __launch_bounds__(256) void hist_kernel(const int* __restrict__ w, int E)
{
    int is64 = block_probe_is64(w, E);
    int e = blockIdx.x * blockDim.x + threadIdx.x;
    if (e >= E) return;
    atomicAdd(&g_count[load_idx(w, e, is64)], 1);
}

__global__ __launch_bounds__(1024) void scan_p1(int n)
{
    __shared__ int wsum[32];
    int t = threadIdx.x;
    int i = blockIdx.x * 1024 + t;
    int v = (i < n) ? g_count[i] : 0;
    if (i < n) g_count[i] = 0;            // self-clear for next call
    int lane = t & 31, w = t >> 5;

    int x = v;
#pragma unroll
    for (int off = 1; off < 32; off <<= 1) {
        int y = __shfl_up_sync(0xffffffffu, x, off);
        if (lane >= off) x += y;
    }
    if (lane == 31) wsum[w] = x;
    __syncthreads();
    if (w == 0) {
        int z = wsum[lane];
#pragma unroll
        for (int off = 1; off < 32; off <<= 1) {
            int y = __shfl_up_sync(0xffffffffu, z, off);
            if (lane >= off) z += y;
        }
        wsum[lane] = z;
    }
    __syncthreads();
    int excl = x - v + (w > 0 ? wsum[w - 1] : 0);
    if (i < n) g_rowptr[i] = excl;
    if (t == 1023) g_bsum[blockIdx.x] = excl + v;
}

__global__ __launch_bounds__(1024) void scan_p3(int nb, int n)
{
    __shared__ int boff[64];
    int t = threadIdx.x;
    if (t < 64) {
        int v = (t < nb) ? g_bsum[t] : 0;
        int lane = t & 31;
        int x = v;
#pragma unroll
        for (int off = 1; off < 32; off <<= 1) {
            int y = __shfl_up_sync(0xffffffffu, x, off);
            if (lane >= off) x += y;
        }
        boff[t] = x - v;
    }
    __syncthreads();
    if (t >= 32 && t < 64)
        boff[t] += boff[31] + g_bsum[31];
    __syncthreads();

    int i = blockIdx.x * 1024 + t;
    if (i < n) {
        int val = g_rowptr[i] + boff[blockIdx.x];
        g_rowptr[i] = val;
        g_cursor[i] = val;
    }
    if (blockIdx.x == 0 && t == 0)
        g_rowptr[n] = boff[nb - 1] + g_bsum[nb - 1];
}

__global__ __launch_bounds__(256) void scatter_kernel(const int* __restrict__ w, int E)
{
    int is64 = block_probe_is64(w, E);
    int e = blockIdx.x * blockDim.x + threadIdx.x;
    if (e >= E) return;
    int src = load_idx(w, e, is64);
    int dst = load_idx(w, E + e, is64);
    int pos = atomicAdd(&g_cursor[src], 1);
    g_col[pos] = dst;
}

// ---------------------------------------------------------------
// layer-1 attention + aggregation + ELU
// TWO warps per node: warp handles head pair hp (heads 2hp, 2hp+1).
// Per edge per lane: one uint2 feature load (2 half2). Lanes 0-15 own
// head 2hp, lanes 16-31 own head 2hp+1. Lane scores head 2hp+(lane&1);
// weight for owned head selected via shfl width-2 with index lane>>4.
// ---------------------------------------------------------------
__global__ __launch_bounds__(256) void agg_heads(int N)
{
    int gw = (blockIdx.x * blockDim.x + threadIdx.x) >> 5;
    int node = gw >> 1;
    int hp = gw & 1;
    int lane = threadIdx.x & 31;
    if (node >= N) return;

    int e0 = g_rowptr[node];
    int e1 = g_rowptr[node + 1];
    float2 s1 = *(const float2*)&g_s1h[node * 4 + 2 * hp];
    float s1q = (lane & 1) ? s1.y : s1.x;
    int sel = lane >> 4;                  // owned head within pair

    float lloc = 0.f;
    float2 acc0 = make_float2(0.f, 0.f);
    float2 acc1 = make_float2(0.f, 0.f);

    const __half2* H = g_H1h;
    int e = e0;
    for (; e + 2 <= e1; e += 2) {
        int da = g_col[e];
        int db = g_col[e + 1];
        float2 s2a = *(const float2*)&g_s2h[da * 4 + 2 * hp];
        float2 s2b = *(const float2*)&g_s2h[db * 4 + 2 * hp];
        uint2 fa = *(const uint2*)(H + (size_t)da * 128 + hp * 64 + 2 * lane);
        uint2 fb = *(const uint2*)(H + (size_t)db * 128 + hp * 64 + 2 * lane);

        float sva = s1q + ((lane & 1) ? s2a.y : s2a.x);
        float sca = -(sva > 0.f ? sva : ALPHA * sva);
        float pa = __expf(sca);
        float svb = s1q + ((lane & 1) ? s2b.y : s2b.x);
        float scb = -(svb > 0.f ? svb : ALPHA * svb);
        float pb = __expf(scb);
        lloc += pa;
        lloc += pb;
        float pma = __shfl_sync(0xffffffffu, pa, sel, 2);
        float pmb = __shfl_sync(0xffffffffu, pb, sel, 2);

        float2 fa0 = __half22float2(*(__half2*)&fa.x);
        float2 fa1 = __half22float2(*(__half2*)&fa.y);
        float2 fb0 = __half22float2(*(__half2*)&fb.x);
        float2 fb1 = __half22float2(*(__half2*)&fb.y);
        acc0.x += pma * fa0.x + pmb * fb0.x;
        acc0.y += pma * fa0.y + pmb * fb0.y;
        acc1.x += pma * fa1.x + pmb * fb1.x;
        acc1.y += pma * fa1.y + pmb * fb1.y;
    }
    if (e < e1) {
        int da = g_col[e];
        float2 s2a = *(const float2*)&g_s2h[da * 4 + 2 * hp];
        uint2 fa = *(const uint2*)(H + (size_t)da * 128 + hp * 64 + 2 * lane);
        float sva = s1q + ((lane & 1) ? s2a.y : s2a.x);
        float sca = -(sva > 0.f ? sva : ALPHA * sva);
        float pa = __expf(sca);
        lloc += pa;
        float pma = __shfl_sync(0xffffffffu, pa, sel, 2);
        float2 fa0 = __half22float2(*(__half2*)&fa.x);
        float2 fa1 = __half22float2(*(__half2*)&fa.y);
        acc0.x += pma * fa0.x;
        acc0.y += pma * fa0.y;
        acc1.x += pma * fa1.x;
        acc1.y += pma * fa1.y;
    }

    float lh = __shfl_sync(0xffffffffu, lloc, sel, 2);
    float inv = (e1 > e0) ? 1.f / lh : 0.f;

    float o0 = acc0.x * inv, o1 = acc0.y * inv;
    float o2 = acc1.x * inv, o3 = acc1.y * inv;
    o0 = (o0 > 0.f) ? o0 : (__expf(o0) - 1.f);
    o1 = (o1 > 0.f) ? o1 : (__expf(o1) - 1.f);
    o2 = (o2 > 0.f) ? o2 : (__expf(o2) - 1.f);
    o3 = (o3 > 0.f) ? o3 : (__expf(o3) - 1.f);

    int myh = 2 * hp + sel;
    __half2 h0 = __floats2half2_rn(o0, o1);
    __half2 h1 = __floats2half2_rn(o2, o3);
    *(uint2*)(g_hcat16 + (size_t)node * 128 + myh * 32 + 2 * (lane & 15)) =
        make_uint2(*(unsigned*)&h0, *(unsigned*)&h1);
}

// ---------------------------------------------------------------
// output-layer aggregation (warp per node, dim 64), 4-edge unroll
// ---------------------------------------------------------------
__global__ __launch_bounds__(256) void agg_out(float* __restrict__ out, int N)
{
    int warp = (blockIdx.x * blockDim.x + threadIdx.x) >> 5;
    int lane = threadIdx.x & 31;
    if (warp >= N) return;

    int e0 = g_rowptr[warp];
    int e1 = g_rowptr[warp + 1];
    float s1 = g_s1o[warp];

    float l = 0.f;
    float2 acc = make_float2(0.f, 0.f);

    int e = e0;
    for (; e + 4 <= e1; e += 4) {
        int d0 = g_col[e], d1i = g_col[e + 1], d2i = g_col[e + 2], d3i = g_col[e + 3];
        float t0 = g_s2o[d0], t1 = g_s2o[d1i], t2 = g_s2o[d2i], t3 = g_s2o[d3i];
        float2 v0 = __half22float2(g_H2h[(size_t)d0 * 32 + lane]);
        float2 v1 = __half22float2(g_H2h[(size_t)d1i * 32 + lane]);
        float2 v2 = __half22float2(g_H2h[(size_t)d2i * 32 + lane]);
        float2 v3 = __half22float2(g_H2h[(size_t)d3i * 32 + lane]);

        float s;
        s = s1 + t0; s = -(s > 0.f ? s : ALPHA * s); float p0 = __expf(s);
        s = s1 + t1; s = -(s > 0.f ? s : ALPHA * s); float p1 = __expf(s);
        s = s1 + t2; s = -(s > 0.f ? s : ALPHA * s); float p2 = __expf(s);
        s = s1 + t3; s = -(s > 0.f ? s : ALPHA * s); float p3 = __expf(s);
        l += p0 + p1 + p2 + p3;
        acc.x += p0 * v0.x + p1 * v1.x + p2 * v2.x + p3 * v3.x;
        acc.y += p0 * v0.y + p1 * v1.y + p2 * v2.y + p3 * v3.y;
    }
    for (; e < e1; e++) {
        int da = g_col[e];
        float s2a = g_s2o[da];
        float2 va = __half22float2(g_H2h[(size_t)da * 32 + lane]);
        float s = s1 + s2a;
        s = -(s > 0.f ? s : ALPHA * s);
        float pa = __expf(s);
        l += pa;
        acc.x += pa * va.x;
        acc.y += pa * va.y;
    }

    float va = 0.f, vb = 0.f;
    if (e1 > e0) {
        float inv = 1.f / l;
        va = acc.x * inv;
        vb = acc.y * inv;
    }
    *(float2*)(out + (size_t)warp * 64 + 2 * lane) = make_float2(va, vb);
}

// ---------------------------------------------------------------
extern "C" void kernel_launch(void* const* d_in, const int* in_sizes, int n_in,
                              void* d_out, int out_size)
{
    const float* x          = (const float*)d_in[0];
    const int*   ei_w       = (const int*)d_in[1];
    const float* W_heads    = (const float*)d_in[2];
    const float* attn_heads = (const float*)d_in[3];
    const float* W_out      = (const float*)d_in[4];
    const float* attn_out   = (const float*)d_in[5];
    float* out = (float*)d_out;

    int N = in_sizes[0] / 128;
    int E = in_sizes[1] / 2;

    int nodeWarpBlocks = (N + 7) / 8;
    int aggHeadBlocks = (2 * N + 7) / 8;      // 2 warps per node
    int edgeBlocks = (E + 255) / 256;
    int scanBlocks = (N + 1023) / 1024;

    // one-time setup (first call is NOT under capture)
    static cudaStream_t sSide = nullptr;
    static cudaEvent_t evFork = nullptr, evJoin = nullptr;
    if (!sSide) {
        cudaStreamCreateWithFlags(&sSide, cudaStreamNonBlocking);
        cudaEventCreateWithFlags(&evFork, cudaEventDisableTiming);
        cudaEventCreateWithFlags(&evJoin, cudaEventDisableTiming);
        cudaFuncSetAttribute(h16_gemm, cudaFuncAttributeMaxDynamicSharedMemorySize, GEMM_SMEM);
    }

    // fork: CSR chain on side stream, GEMM1 on main stream
    cudaEventRecord(evFork, 0);
    cudaStreamWaitEvent(sSide, evFork, 0);

    hist_kernel<<<edgeBlocks, 256, 0, sSide>>>(ei_w, E);     // 1
    scan_p1<<<scanBlocks, 1024, 0, sSide>>>(N);              // 2
    scan_p3<<<scanBlocks, 1024, 0, sSide>>>(scanBlocks, N);  // 3

    // GEMM1 (+ fused svec + fp16 mirror): 4 head tiles — launch 4 (ncu slot)
    dim3 g1((N + 255) / 256, 4);
    h16_gemm<<<g1, 256, GEMM_SMEM>>>(x, 128, W_heads, attn_heads, 0, N, 128);

    scatter_kernel<<<edgeBlocks, 256, 0, sSide>>>(ei_w, E);  // 5
    cudaEventRecord(evJoin, sSide);

    cudaStreamWaitEvent(0, evJoin, 0);

    // layer-1 softmax+aggregate+ELU -> g_hcat16 (2 warps/node)
    agg_heads<<<aggHeadBlocks, 256>>>(N);

    // GEMM2 (+ fused svec_out + fp16 mirror)
    dim3 g2((N + 255) / 256, 1);
    h16_gemm<<<g2, 256, GEMM_SMEM>>>(nullptr, 0, W_out, attn_out, 1, N, 256);

    // final aggregation
    agg_out<<<nodeWarpBlocks, 256>>>(out, N);
}

// round 11
// speedup vs baseline: 1.0922x; 1.0922x over previous
#include <cuda_runtime.h>
#include <cuda_fp16.h>
#include <math.h>

#define NMAX 50000
#define EMAX 800000
#define ALPHA 0.01f

// ---- static scratch (no allocations allowed) ----
__device__ __half2 g_H1h[(size_t)NMAX * 128]; // layer-1 features fp16, head-major (256 halves/row)
__device__ __half2 g_H2h[(size_t)NMAX * 32];  // layer-2 features fp16 (64 halves/row)
__device__ __half2 g_hcat16[(size_t)NMAX * 128]; // elu(attn out) fp16, layer-2 input
__device__ float g_s1h[NMAX * 4];
__device__ float g_s2h[NMAX * 4];
__device__ float g_s1o[NMAX];
__device__ float g_s2o[NMAX];
__device__ int   g_count[NMAX];               // .bss zero-init; scan_p1 re-zeroes each call
__device__ int   g_rowptr[NMAX + 1];
__device__ int   g_cursor[NMAX];
__device__ int   g_col[EMAX];
__device__ int   g_bsum[64];

// ---------------------------------------------------------------
__device__ __forceinline__ int block_probe_is64(const int* __restrict__ w, int E)
{
    int t = threadIdx.x;
    int nElem = (E < 128) ? E : 128;
    int ok = 1;
    if (t < nElem) ok = (w[2 * t + 1] == 0);
    return __syncthreads_and(ok);
}

__device__ __forceinline__ int load_idx(const int* __restrict__ w, int pos, int is64)
{
    return is64 ? w[2 * pos] : w[pos];
}

// ---------------------------------------------------------------
// fp16 tensor-core GEMM (m16n8k16, fp32 accum), 256x64 block,
// warp tile 32x64. B converted fp32->fp16 + transposed during staging.
// Fused epilogue: fp16 mirror + score dots.
// layer 0: A = A32 (x, fp32), B = W32 + head*8192 ([k=128][n=64])
// layer 1: A = g_hcat16 (fp16), B = W32 ([k=256][n=64])
// ---------------------------------------------------------------
__device__ __forceinline__ void mma16816(
    float* d, unsigned a0, unsigned a1, unsigned a2, unsigned a3,
    unsigned b0, unsigned b1)
{
    asm volatile(
        "mma.sync.aligned.m16n8k16.row.col.f32.f16.f16.f32 "
        "{%0,%1,%2,%3}, {%4,%5,%6,%7}, {%8,%9}, {%0,%1,%2,%3};\n"
        : "+f"(d[0]), "+f"(d[1]), "+f"(d[2]), "+f"(d[3])
        : "r"(a0), "r"(a1), "r"(a2), "r"(a3), "r"(b0), "r"(b1));
}

#define ROWW 68                                  // smem words per row (136 halves)
#define GEMM_SMEM ((64 * ROWW + 256 * ROWW) * 4) // B + A = 87040 B

__global__ __launch_bounds__(256, 2) void h16_gemm(
    const float* __restrict__ A32, int lda,
    const float* __restrict__ W32,
    const float* __restrict__ attn, int layer, int M, int K)
{
    extern __shared__ unsigned dsm[];
    unsigned* Bs = dsm;                    // [64][ROWW]
    unsigned* As = dsm + 64 * ROWW;        // [256][ROWW]

    int head = blockIdx.y;
    const float* Bsrc = (layer == 0) ? W32 + (size_t)head * 8192 : W32;
    const unsigned* A16 = (const unsigned*)g_hcat16;      // used when A32==null
    const int ldaW = 128;

    int row0 = blockIdx.x * 256;

    int tid = threadIdx.x;
    int lane = tid & 31, w = tid >> 5;
    int gid = lane >> 2, tig = lane & 3;

    float acc0[8][4], acc1[8][4];
#pragma unroll
    for (int i = 0; i < 8; i++)
#pragma unroll
        for (int j = 0; j < 4; j++) { acc0[i][j] = 0.f; acc1[i][j] = 0.f; }

    for (int kc = 0; kc < K; kc += 128) {
        if (kc) __syncthreads();
        // stage B chunk [64 n][128 k]: transpose + cvt from fp32 [k][64 n]
#pragma unroll
        for (int i = 0; i < 32; i++) {
            int u = tid + i * 256;         // 0..8191
            int k = u >> 6, n = u & 63;
            __half hv = __float2half_rn(Bsrc[(size_t)(kc + k) * 64 + n]);
            ((__half*)Bs)[n * (ROWW * 2) + k] = hv;
        }
        // stage A chunk: 256 rows x 64 words
        if (A32) {
#pragma unroll
            for (int i = 0; i < 32; i++) {
                int u = tid + i * 256;
                int row = u >> 5, c4 = u & 31;
                float4 av = make_float4(0.f, 0.f, 0.f, 0.f);
                if (row0 + row < M)
                    av = *(const float4*)(A32 + (size_t)(row0 + row) * lda + kc + c4 * 4);
                __half2 lo = __floats2half2_rn(av.x, av.y);
                __half2 hi = __floats2half2_rn(av.z, av.w);
                *(uint2*)&As[row * ROWW + 2 * c4] =
                    make_uint2(*(unsigned*)&lo, *(unsigned*)&hi);
            }
        } else {
#pragma unroll
            for (int i = 0; i < 32; i++) {
                int u = tid + i * 256;
                int row = u >> 5, w2 = u & 31;
                uint2 v = make_uint2(0u, 0u);
                if (row0 + row < M)
                    v = *(const uint2*)(A16 + (size_t)(row0 + row) * ldaW + (kc >> 1) + 2 * w2);
                *(uint2*)&As[row * ROWW + 2 * w2] = v;
            }
        }
        __syncthreads();

#pragma unroll
        for (int s = 0; s < 8; s++) {          // 8 k16 steps per 128-half chunk
            int ws = s * 8;
            int rA = (w * 32 + gid) * ROWW;
            unsigned a00 = As[rA + ws + tig];
            unsigned a01 = As[rA + 8 * ROWW + ws + tig];
            unsigned a02 = As[rA + ws + 4 + tig];
            unsigned a03 = As[rA + 8 * ROWW + ws + 4 + tig];
            unsigned a10 = As[rA + 16 * ROWW + ws + tig];
            unsigned a11 = As[rA + 24 * ROWW + ws + tig];
            unsigned a12 = As[rA + 16 * ROWW + ws + 4 + tig];
            unsigned a13 = As[rA + 24 * ROWW + ws + 4 + tig];
#pragma unroll
            for (int n0 = 0; n0 < 8; n0++) {
                int rB = (n0 * 8 + gid) * ROWW + ws + tig;
                unsigned b0 = Bs[rB];
                unsigned b1 = Bs[rB + 4];
                mma16816(acc0[n0], a00, a01, a02, a03, b0, b1);
                mma16816(acc1[n0], a10, a11, a12, a13, b0, b1);
            }
        }
    }

    // ---- fused epilogue ----
    __half2* Hh2;
    int ldH2, colBase2, sStride, sOff;
    float *s1g, *s2g;
    const float* a1;
    if (layer == 0) {
        Hh2 = g_H1h; ldH2 = 128; colBase2 = head * 32;
        sStride = 4; sOff = head; s1g = g_s1h; s2g = g_s2h;
        a1 = attn + head * 128;
    } else {
        Hh2 = g_H2h; ldH2 = 32; colBase2 = 0;
        sStride = 1; sOff = 0; s1g = g_s1o; s2g = g_s2o;
        a1 = attn;
    }
    const float* a2v = a1 + 64;

    int rb = row0 + w * 32 + gid;
    int rows[4] = {rb, rb + 8, rb + 16, rb + 24};

    float d1[4] = {0.f, 0.f, 0.f, 0.f};
    float d2[4] = {0.f, 0.f, 0.f, 0.f};
#pragma unroll
    for (int n0 = 0; n0 < 8; n0++) {
        int c0 = n0 * 8 + 2 * tig;
        float w10 = __ldg(a1 + c0), w11 = __ldg(a1 + c0 + 1);
        float w20 = __ldg(a2v + c0), w21 = __ldg(a2v + c0 + 1);
        d1[0] += acc0[n0][0] * w10 + acc0[n0][1] * w11;
        d2[0] += acc0[n0][0] * w20 + acc0[n0][1] * w21;
        d1[1] += acc0[n0][2] * w10 + acc0[n0][3] * w11;
        d2[1] += acc0[n0][2] * w20 + acc0[n0][3] * w21;
        d1[2] += acc1[n0][0] * w10 + acc1[n0][1] * w11;
        d2[2] += acc1[n0][0] * w20 + acc1[n0][1] * w21;
        d1[3] += acc1[n0][2] * w10 + acc1[n0][3] * w11;
        d2[3] += acc1[n0][2] * w20 + acc1[n0][3] * w21;
    }
#pragma unroll
    for (int f = 0; f < 4; f++) {
#pragma unroll
        for (int off = 1; off < 4; off <<= 1) {
            d1[f] += __shfl_xor_sync(0xffffffffu, d1[f], off);
            d2[f] += __shfl_xor_sync(0xffffffffu, d2[f], off);
        }
    }
    if (tig == 0) {
#pragma unroll
        for (int f = 0; f < 4; f++) {
            if (rows[f] < M) {
                s1g[rows[f] * sStride + sOff] = d1[f];
                s2g[rows[f] * sStride + sOff] = d2[f];
            }
        }
    }

#pragma unroll
    for (int n0 = 0; n0 < 8; n0++) {
        int cc = colBase2 + n0 * 4 + tig;
        if (rows[0] < M)
            Hh2[(size_t)rows[0] * ldH2 + cc] = __floats2half2_rn(acc0[n0][0], acc0[n0][1]);
        if (rows[1] < M)
            Hh2[(size_t)rows[1] * ldH2 + cc] = __floats2half2_rn(acc0[n0][2], acc0[n0][3]);
        if (rows[2] < M)
            Hh2[(size_t)rows[2] * ldH2 + cc] = __floats2half2_rn(acc1[n0][0], acc1[n0][1]);
        if (rows[3] < M)
            Hh2[(size_t)rows[3] * ldH2 + cc] = __floats2half2_rn(acc1[n0][2], acc1[n0][3]);
    }
}

// ---------------------------------------------------------------
// CSR build
// ---------------------------------------------------------------
__global__ __launch_bounds__(256) void hist_kernel(const int* __restrict__ w, int E)
{
    int is64 = block_probe_is64(w, E);
    int e = blockIdx.x * blockDim.x + threadIdx.x;
    if (e >= E) return;
    atomicAdd(&g_count[load_idx(w, e, is64)], 1);
}

__global__ __launch_bounds__(1024) void scan_p1(int n)
{
    __shared__ int wsum[32];
    int t = threadIdx.x;
    int i = blockIdx.x * 1024 + t;
    int v = (i < n) ? g_count[i] : 0;
    if (i < n) g_count[i] = 0;            // self-clear for next call
    int lane = t & 31, w = t >> 5;

    int x = v;
#pragma unroll
    for (int off = 1; off < 32; off <<= 1) {
        int y = __shfl_up_sync(0xffffffffu, x, off);
        if (lane >= off) x += y;
    }
    if (lane == 31) wsum[w] = x;
    __syncthreads();
    if (w == 0) {
        int z = wsum[lane];
#pragma unroll
        for (int off = 1; off < 32; off <<= 1) {
            int y = __shfl_up_sync(0xffffffffu, z, off);
            if (lane >= off) z += y;
        }
        wsum[lane] = z;
    }
    __syncthreads();
    int excl = x - v + (w > 0 ? wsum[w - 1] : 0);
    if (i < n) g_rowptr[i] = excl;
    if (t == 1023) g_bsum[blockIdx.x] = excl + v;
}

__global__ __launch_bounds__(1024) void scan_p3(int nb, int n)
{
    __shared__ int boff[64];
    int t = threadIdx.x;
    if (t < 64) {
        int v = (t < nb) ? g_bsum[t] : 0;
        int lane = t & 31;
        int x = v;
#pragma unroll
        for (int off = 1; off < 32; off <<= 1) {
            int y = __shfl_up_sync(0xffffffffu, x, off);
            if (lane >= off) x += y;
        }
        boff[t] = x - v;
    }
    __syncthreads();
    if (t >= 32 && t < 64)
        boff[t] += boff[31] + g_bsum[31];
    __syncthreads();

    int i = blockIdx.x * 1024 + t;
    if (i < n) {
        int val = g_rowptr[i] + boff[blockIdx.x];
        g_rowptr[i] = val;
        g_cursor[i] = val;
    }
    if (blockIdx.x == 0 && t == 0)
        g_rowptr[n] = boff[nb - 1] + g_bsum[nb - 1];
}

__global__ __launch_bounds__(256) void scatter_kernel(const int* __restrict__ w, int E)
{
    int is64 = block_probe_is64(w, E);
    int e = blockIdx.x * blockDim.x + threadIdx.x;
    if (e >= E) return;
    int src = load_idx(w, e, is64);
    int dst = load_idx(w, E + e, is64);
    int pos = atomicAdd(&g_cursor[src], 1);
    g_col[pos] = dst;
}

// ---------------------------------------------------------------
// layer-1 attention + aggregation + ELU (warp per node, 4 heads)
// single LDG.128/lane feature gather; lane L owns head L>>3, half2
// columns 4(L&7)..4(L&7)+3; scores on lanes hq=L&3; 2-edge unroll.
// (R9 best-known-good version)
// ---------------------------------------------------------------
__device__ __forceinline__ float sel4(float4 v, int q)
{
    float r = v.x;
    r = (q == 1) ? v.y : r;
    r = (q == 2) ? v.z : r;
    r = (q == 3) ? v.w : r;
    return r;
}

__device__ __forceinline__ void acc_f4(float2* acc, float pm, float4 hv)
{
    __half2 q0 = *(__half2*)&hv.x;
    __half2 q1 = *(__half2*)&hv.y;
    __half2 q2 = *(__half2*)&hv.z;
    __half2 q3 = *(__half2*)&hv.w;
    float2 f0 = __half22float2(q0);
    float2 f1 = __half22float2(q1);
    float2 f2 = __half22float2(q2);
    float2 f3 = __half22float2(q3);
    acc[0].x += pm * f0.x; acc[0].y += pm * f0.y;
    acc[1].x += pm * f1.x; acc[1].y += pm * f1.y;
    acc[2].x += pm * f2.x; acc[2].y += pm * f2.y;
    acc[3].x += pm * f3.x; acc[3].y += pm * f3.y;
}

__global__ __launch_bounds__(256) void agg_heads(int N)
{
    int warp = (blockIdx.x * blockDim.x + threadIdx.x) >> 5;
    int lane = threadIdx.x & 31;
    if (warp >= N) return;

    int e0 = g_rowptr[warp];
    int e1 = g_rowptr[warp + 1];
    int hq = lane & 3;                 // head this lane scores
    int myhead = lane >> 3;            // head this lane accumulates
    float4 s1v = *(const float4*)&g_s1h[warp * 4];
    float s1q = sel4(s1v, hq);

    float lloc = 0.f;
    float2 acc[4];
#pragma unroll
    for (int j = 0; j < 4; j++) acc[j] = make_float2(0.f, 0.f);

    int e = e0;
    for (; e + 2 <= e1; e += 2) {
        int da = g_col[e];
        int db = g_col[e + 1];
        float4 s2a = *(const float4*)&g_s2h[da * 4];
        float4 s2b = *(const float4*)&g_s2h[db * 4];
        float4 ha = ((const float4*)(g_H1h + (size_t)da * 128))[lane];
        float4 hb = ((const float4*)(g_H1h + (size_t)db * 128))[lane];

        float sva = s1q + sel4(s2a, hq);
        float sca = -(sva > 0.f ? sva : ALPHA * sva);
        float pa = __expf(sca);
        float svb = s1q + sel4(s2b, hq);
        float scb = -(svb > 0.f ? svb : ALPHA * svb);
        float pb = __expf(scb);
        lloc += pa;
        lloc += pb;
        float pma = __shfl_sync(0xffffffffu, pa, myhead, 4);
        float pmb = __shfl_sync(0xffffffffu, pb, myhead, 4);

        acc_f4(acc, pma, ha);
        acc_f4(acc, pmb, hb);
    }
    if (e < e1) {
        int da = g_col[e];
        float4 s2a = *(const float4*)&g_s2h[da * 4];
        float4 ha = ((const float4*)(g_H1h + (size_t)da * 128))[lane];
        float sva = s1q + sel4(s2a, hq);
        float sca = -(sva > 0.f ? sva : ALPHA * sva);
        float pa = __expf(sca);
        lloc += pa;
        float pma = __shfl_sync(0xffffffffu, pa, myhead, 4);
        acc_f4(acc, pma, ha);
    }

    float lh = __shfl_sync(0xffffffffu, lloc, myhead, 4);
    float inv = (e1 > e0) ? 1.f / lh : 0.f;

    float o[8];
#pragma unroll
    for (int j = 0; j < 4; j++) {
        o[2 * j]     = acc[j].x * inv;
        o[2 * j + 1] = acc[j].y * inv;
    }
#pragma unroll
    for (int j = 0; j < 8; j++)
        o[j] = (o[j] > 0.f) ? o[j] : (__expf(o[j]) - 1.f);   // ELU

    __half2 oh[4];
#pragma unroll
    for (int j = 0; j < 4; j++)
        oh[j] = __floats2half2_rn(o[2 * j], o[2 * j + 1]);
    __half2* op = g_hcat16 + (size_t)warp * 128 + myhead * 32 + 4 * (lane & 7);
    op[0] = oh[0]; op[1] = oh[1]; op[2] = oh[2]; op[3] = oh[3];
}

// ---------------------------------------------------------------
// output-layer aggregation (warp per node, dim 64), 4-edge unroll
// ---------------------------------------------------------------
__global__ __launch_bounds__(256) void agg_out(float* __restrict__ out, int N)
{
    int warp = (blockIdx.x * blockDim.x + threadIdx.x) >> 5;
    int lane = threadIdx.x & 31;
    if (warp >= N) return;

    int e0 = g_rowptr[warp];
    int e1 = g_rowptr[warp + 1];
    float s1 = g_s1o[warp];

    float l = 0.f;
    float2 acc = make_float2(0.f, 0.f);

    int e = e0;
    for (; e + 4 <= e1; e += 4) {
        int d0 = g_col[e], d1i = g_col[e + 1], d2i = g_col[e + 2], d3i = g_col[e + 3];
        float t0 = g_s2o[d0], t1 = g_s2o[d1i], t2 = g_s2o[d2i], t3 = g_s2o[d3i];
        float2 v0 = __half22float2(g_H2h[(size_t)d0 * 32 + lane]);
        float2 v1 = __half22float2(g_H2h[(size_t)d1i * 32 + lane]);
        float2 v2 = __half22float2(g_H2h[(size_t)d2i * 32 + lane]);
        float2 v3 = __half22float2(g_H2h[(size_t)d3i * 32 + lane]);

        float s;
        s = s1 + t0; s = -(s > 0.f ? s : ALPHA * s); float p0 = __expf(s);
        s = s1 + t1; s = -(s > 0.f ? s : ALPHA * s); float p1 = __expf(s);
        s = s1 + t2; s = -(s > 0.f ? s : ALPHA * s); float p2 = __expf(s);
        s = s1 + t3; s = -(s > 0.f ? s : ALPHA * s); float p3 = __expf(s);
        l += p0 + p1 + p2 + p3;
        acc.x += p0 * v0.x + p1 * v1.x + p2 * v2.x + p3 * v3.x;
        acc.y += p0 * v0.y + p1 * v1.y + p2 * v2.y + p3 * v3.y;
    }
    for (; e < e1; e++) {
        int da = g_col[e];
        float s2a = g_s2o[da];
        float2 va = __half22float2(g_H2h[(size_t)da * 32 + lane]);
        float s = s1 + s2a;
        s = -(s > 0.f ? s : ALPHA * s);
        float pa = __expf(s);
        l += pa;
        acc.x += pa * va.x;
        acc.y += pa * va.y;
    }

    float va = 0.f, vb = 0.f;
    if (e1 > e0) {
        float inv = 1.f / l;
        va = acc.x * inv;
        vb = acc.y * inv;
    }
    *(float2*)(out + (size_t)warp * 64 + 2 * lane) = make_float2(va, vb);
}

// ---------------------------------------------------------------
extern "C" void kernel_launch(void* const* d_in, const int* in_sizes, int n_in,
                              void* d_out, int out_size)
{
    const float* x          = (const float*)d_in[0];
    const int*   ei_w       = (const int*)d_in[1];
    const float* W_heads    = (const float*)d_in[2];
    const float* attn_heads = (const float*)d_in[3];
    const float* W_out      = (const float*)d_in[4];
    const float* attn_out   = (const float*)d_in[5];
    float* out = (float*)d_out;

    int N = in_sizes[0] / 128;
    int E = in_sizes[1] / 2;

    int nodeWarpBlocks = (N + 7) / 8;
    int edgeBlocks = (E + 255) / 256;
    int scanBlocks = (N + 1023) / 1024;

    // one-time setup (first call is NOT under capture)
    static cudaStream_t sSide = nullptr;
    static cudaEvent_t evFork = nullptr, evJoin = nullptr;
    if (!sSide) {
        cudaStreamCreateWithFlags(&sSide, cudaStreamNonBlocking);
        cudaEventCreateWithFlags(&evFork, cudaEventDisableTiming);
        cudaEventCreateWithFlags(&evJoin, cudaEventDisableTiming);
        cudaFuncSetAttribute(h16_gemm, cudaFuncAttributeMaxDynamicSharedMemorySize, GEMM_SMEM);
    }

    // fork: CSR chain on side stream, GEMM1 on main stream
    cudaEventRecord(evFork, 0);
    cudaStreamWaitEvent(sSide, evFork, 0);

    hist_kernel<<<edgeBlocks, 256, 0, sSide>>>(ei_w, E);     // 1
    scan_p1<<<scanBlocks, 1024, 0, sSide>>>(N);              // 2
    scan_p3<<<scanBlocks, 1024, 0, sSide>>>(scanBlocks, N);  // 3

    // GEMM1 (+ fused svec + fp16 mirror): 4 head tiles — launch 4 (ncu slot)
    dim3 g1((N + 255) / 256, 4);
    h16_gemm<<<g1, 256, GEMM_SMEM>>>(x, 128, W_heads, attn_heads, 0, N, 128);

    scatter_kernel<<<edgeBlocks, 256, 0, sSide>>>(ei_w, E);  // 5
    cudaEventRecord(evJoin, sSide);

    cudaStreamWaitEvent(0, evJoin, 0);

    // layer-1 softmax+aggregate+ELU -> g_hcat16 (1 warp/node, float4 gather)
    agg_heads<<<nodeWarpBlocks, 256>>>(N);

    // GEMM2 (+ fused svec_out + fp16 mirror)
    dim3 g2((N + 255) / 256, 1);
    h16_gemm<<<g2, 256, GEMM_SMEM>>>(nullptr, 0, W_out, attn_out, 1, N, 256);

    // final aggregation
    agg_out<<<nodeWarpBlocks, 256>>>(out, N);
}

// round 12
// speedup vs baseline: 1.1172x; 1.0228x over previous
#include <cuda_runtime.h>
#include <cuda_fp16.h>
#include <math.h>

#define NMAX 50000
#define EMAX 800000
#define ALPHA 0.01f

// ---- static scratch (no allocations allowed) ----
__device__ __half2 g_H1h[(size_t)NMAX * 128]; // layer-1 features fp16, head-major (256 halves/row)
__device__ __half2 g_H2h[(size_t)NMAX * 32];  // layer-2 features fp16 (64 halves/row)
__device__ __half2 g_hcat16[(size_t)NMAX * 128]; // elu(attn out) fp16, layer-2 input
__device__ float g_s1h[NMAX * 4];
__device__ float g_s2h[NMAX * 4];
__device__ float g_s1o[NMAX];
__device__ float g_s2o[NMAX];
__device__ int   g_count[NMAX];               // .bss zero-init; scan_p1 re-zeroes each call
__device__ int   g_rowptr[NMAX + 1];
__device__ int   g_cursor[NMAX];
__device__ int   g_col[EMAX];
__device__ int   g_bsum[64];

// ---------------------------------------------------------------
__device__ __forceinline__ int block_probe_is64(const int* __restrict__ w, int E)
{
    int t = threadIdx.x;
    int nElem = (E < 128) ? E : 128;
    int ok = 1;
    if (t < nElem) ok = (w[2 * t + 1] == 0);
    return __syncthreads_and(ok);
}

__device__ __forceinline__ int load_idx(const int* __restrict__ w, int pos, int is64)
{
    return is64 ? w[2 * pos] : w[pos];
}

// ---------------------------------------------------------------
// fp16 tensor-core GEMM (m16n8k16, fp32 accum), 256x64 block,
// warp tile 32x64, ldmatrix.x4 smem reads.
// B converted fp32->fp16 + transposed during staging.
// Fused epilogue: fp16 mirror + score dots.
// layer 0: A = A32 (x, fp32), B = W32 + head*8192 ([k=128][n=64])
// layer 1: A = g_hcat16 (fp16), B = W32 ([k=256][n=64])
// ---------------------------------------------------------------
__device__ __forceinline__ void mma16816(
    float* d, unsigned a0, unsigned a1, unsigned a2, unsigned a3,
    unsigned b0, unsigned b1)
{
    asm volatile(
        "mma.sync.aligned.m16n8k16.row.col.f32.f16.f16.f32 "
        "{%0,%1,%2,%3}, {%4,%5,%6,%7}, {%8,%9}, {%0,%1,%2,%3};\n"
        : "+f"(d[0]), "+f"(d[1]), "+f"(d[2]), "+f"(d[3])
        : "r"(a0), "r"(a1), "r"(a2), "r"(a3), "r"(b0), "r"(b1));
}

#define LDSM4(r0, r1, r2, r3, addr) \
    asm volatile("ldmatrix.sync.aligned.m8n8.x4.shared.b16 {%0,%1,%2,%3}, [%4];" \
        : "=r"(r0), "=r"(r1), "=r"(r2), "=r"(r3) : "r"(addr))

#define ROWW 68                                  // smem words per row (136 halves)
#define GEMM_SMEM ((64 * ROWW + 256 * ROWW) * 4) // B + A = 87040 B

__global__ __launch_bounds__(256, 2) void h16_gemm(
    const float* __restrict__ A32, int lda,
    const float* __restrict__ W32,
    const float* __restrict__ attn, int layer, int M, int K)
{
    extern __shared__ unsigned dsm[];
    unsigned* Bs = dsm;                    // [64][ROWW]
    unsigned* As = dsm + 64 * ROWW;        // [256][ROWW]

    int head = blockIdx.y;
    const float* Bsrc = (layer == 0) ? W32 + (size_t)head * 8192 : W32;
    const unsigned* A16 = (const unsigned*)g_hcat16;      // used when A32==null
    const int ldaW = 128;

    int row0 = blockIdx.x * 256;

    int tid = threadIdx.x;
    int lane = tid & 31, w = tid >> 5;
    int gid = lane >> 2, tig = lane & 3;

    // ldmatrix per-lane base addresses (bytes, shared space)
    unsigned smemB = (unsigned)__cvta_generic_to_shared(dsm);
    int aRow = w * 32 + (lane & 15);
    int aK = (lane & 16) ? 4 : 0;
    unsigned addrA0 = smemB + (unsigned)(64 * ROWW + aRow * ROWW + aK) * 4;
    unsigned addrA1 = addrA0 + 16 * ROWW * 4;
    int bRow = (lane & 7) + ((lane & 16) ? 8 : 0);
    int bK = (lane & 8) ? 4 : 0;
    unsigned addrB = smemB + (unsigned)(bRow * ROWW + bK) * 4;

    float acc0[8][4], acc1[8][4];
#pragma unroll
    for (int i = 0; i < 8; i++)
#pragma unroll
        for (int j = 0; j < 4; j++) { acc0[i][j] = 0.f; acc1[i][j] = 0.f; }

    for (int kc = 0; kc < K; kc += 128) {
        if (kc) __syncthreads();
        // stage B chunk [64 n][128 k]: transpose + cvt from fp32 [k][64 n]
#pragma unroll
        for (int i = 0; i < 32; i++) {
            int u = tid + i * 256;         // 0..8191
            int k = u >> 6, n = u & 63;
            __half hv = __float2half_rn(Bsrc[(size_t)(kc + k) * 64 + n]);
            ((__half*)Bs)[n * (ROWW * 2) + k] = hv;
        }
        // stage A chunk: 256 rows x 64 words
        if (A32) {
#pragma unroll
            for (int i = 0; i < 32; i++) {
                int u = tid + i * 256;
                int row = u >> 5, c4 = u & 31;
                float4 av = make_float4(0.f, 0.f, 0.f, 0.f);
                if (row0 + row < M)
                    av = *(const float4*)(A32 + (size_t)(row0 + row) * lda + kc + c4 * 4);
                __half2 lo = __floats2half2_rn(av.x, av.y);
                __half2 hi = __floats2half2_rn(av.z, av.w);
                *(uint2*)&As[row * ROWW + 2 * c4] =
                    make_uint2(*(unsigned*)&lo, *(unsigned*)&hi);
            }
        } else {
#pragma unroll
            for (int i = 0; i < 32; i++) {
                int u = tid + i * 256;
                int row = u >> 5, w2 = u & 31;
                uint2 v = make_uint2(0u, 0u);
                if (row0 + row < M)
                    v = *(const uint2*)(A16 + (size_t)(row0 + row) * ldaW + (kc >> 1) + 2 * w2);
                *(uint2*)&As[row * ROWW + 2 * w2] = v;
            }
        }
        __syncthreads();

#pragma unroll
        for (int s = 0; s < 8; s++) {          // 8 k16 steps per 128-half chunk
            unsigned off = s * 32;             // 8 words = 32 bytes per step
            unsigned a00, a01, a02, a03, a10, a11, a12, a13;
            LDSM4(a00, a01, a02, a03, addrA0 + off);
            LDSM4(a10, a11, a12, a13, addrA1 + off);
#pragma unroll
            for (int np = 0; np < 4; np++) {
                unsigned b0, b1, b2, b3;
                LDSM4(b0, b1, b2, b3, addrB + off + np * (16 * ROWW * 4));
                mma16816(acc0[2 * np],     a00, a01, a02, a03, b0, b1);
                mma16816(acc1[2 * np],     a10, a11, a12, a13, b0, b1);
                mma16816(acc0[2 * np + 1], a00, a01, a02, a03, b2, b3);
                mma16816(acc1[2 * np + 1], a10, a11, a12, a13, b2, b3);
            }
        }
    }

    // ---- fused epilogue ----
    __half2* Hh2;
    int ldH2, colBase2, sStride, sOff;
    float *s1g, *s2g;
    const float* a1;
    if (layer == 0) {
        Hh2 = g_H1h; ldH2 = 128; colBase2 = head * 32;
        sStride = 4; sOff = head; s1g = g_s1h; s2g = g_s2h;
        a1 = attn + head * 128;
    } else {
        Hh2 = g_H2h; ldH2 = 32; colBase2 = 0;
        sStride = 1; sOff = 0; s1g = g_s1o; s2g = g_s2o;
        a1 = attn;
    }
    const float* a2v = a1 + 64;

    int rb = row0 + w * 32 + gid;
    int rows[4] = {rb, rb + 8, rb + 16, rb + 24};

    float d1[4] = {0.f, 0.f, 0.f, 0.f};
    float d2[4] = {0.f, 0.f, 0.f, 0.f};
#pragma unroll
    for (int n0 = 0; n0 < 8; n0++) {
        int c0 = n0 * 8 + 2 * tig;
        float w10 = __ldg(a1 + c0), w11 = __ldg(a1 + c0 + 1);
        float w20 = __ldg(a2v + c0), w21 = __ldg(a2v + c0 + 1);
        d1[0] += acc0[n0][0] * w10 + acc0[n0][1] * w11;
        d2[0] += acc0[n0][0] * w20 + acc0[n0][1] * w21;
        d1[1] += acc0[n0][2] * w10 + acc0[n0][3] * w11;
        d2[1] += acc0[n0][2] * w20 + acc0[n0][3] * w21;
        d1[2] += acc1[n0][0] * w10 + acc1[n0][1] * w11;
        d2[2] += acc1[n0][0] * w20 + acc1[n0][1] * w21;
        d1[3] += acc1[n0][2] * w10 + acc1[n0][3] * w11;
        d2[3] += acc1[n0][2] * w20 + acc1[n0][3] * w21;
    }
#pragma unroll
    for (int f = 0; f < 4; f++) {
#pragma unroll
        for (int off = 1; off < 4; off <<= 1) {
            d1[f] += __shfl_xor_sync(0xffffffffu, d1[f], off);
            d2[f] += __shfl_xor_sync(0xffffffffu, d2[f], off);
        }
    }
    if (tig == 0) {
#pragma unroll
        for (int f = 0; f < 4; f++) {
            if (rows[f] < M) {
                s1g[rows[f] * sStride + sOff] = d1[f];
                s2g[rows[f] * sStride + sOff] = d2[f];
            }
        }
    }

#pragma unroll
    for (int n0 = 0; n0 < 8; n0++) {
        int cc = colBase2 + n0 * 4 + tig;
        if (rows[0] < M)
            Hh2[(size_t)rows[0] * ldH2 + cc] = __floats2half2_rn(acc0[n0][0], acc0[n0][1]);
        if (rows[1] < M)
            Hh2[(size_t)rows[1] * ldH2 + cc] = __floats2half2_rn(acc0[n0][2], acc0[n0][3]);
        if (rows[2] < M)
            Hh2[(size_t)rows[2] * ldH2 + cc] = __floats2half2_rn(acc1[n0][0], acc1[n0][1]);
        if (rows[3] < M)
            Hh2[(size_t)rows[3] * ldH2 + cc] = __floats2half2_rn(acc1[n0][2], acc1[n0][3]);
    }
}

// ---------------------------------------------------------------
// CSR build
// ---------------------------------------------------------------
__global__ __launch_bounds__(256) void hist_kernel(const int* __restrict__ w, int E)
{
    int is64 = block_probe_is64(w, E);
    int e = blockIdx.x * blockDim.x + threadIdx.x;
    if (e >= E) return;
    atomicAdd(&g_count[load_idx(w, e, is64)], 1);
}

__global__ __launch_bounds__(1024) void scan_p1(int n)
{
    __shared__ int wsum[32];
    int t = threadIdx.x;
    int i = blockIdx.x * 1024 + t;
    int v = (i < n) ? g_count[i] : 0;
    if (i < n) g_count[i] = 0;            // self-clear for next call
    int lane = t & 31, w = t >> 5;

    int x = v;
#pragma unroll
    for (int off = 1; off < 32; off <<= 1) {
        int y = __shfl_up_sync(0xffffffffu, x, off);
        if (lane >= off) x += y;
    }
    if (lane == 31) wsum[w] = x;
    __syncthreads();
    if (w == 0) {
        int z = wsum[lane];
#pragma unroll
        for (int off = 1; off < 32; off <<= 1) {
            int y = __shfl_up_sync(0xffffffffu, z, off);
            if (lane >= off) z += y;
        }
        wsum[lane] = z;
    }
    __syncthreads();
    int excl = x - v + (w > 0 ? wsum[w - 1] : 0);
    if (i < n) g_rowptr[i] = excl;
    if (t == 1023) g_bsum[blockIdx.x] = excl + v;
}

__global__ __launch_bounds__(1024) void scan_p3(int nb, int n)
{
    __shared__ int boff[64];
    int t = threadIdx.x;
    if (t < 64) {
        int v = (t < nb) ? g_bsum[t] : 0;
        int lane = t & 31;
        int x = v;
#pragma unroll
        for (int off = 1; off < 32; off <<= 1) {
            int y = __shfl_up_sync(0xffffffffu, x, off);
            if (lane >= off) x += y;
        }
        boff[t] = x - v;
    }
    __syncthreads();
    if (t >= 32 && t < 64)
        boff[t] += boff[31] + g_bsum[31];
    __syncthreads();

    int i = blockIdx.x * 1024 + t;
    if (i < n) {
        int val = g_rowptr[i] + boff[blockIdx.x];
        g_rowptr[i] = val;
        g_cursor[i] = val;
    }
    if (blockIdx.x == 0 && t == 0)
        g_rowptr[n] = boff[nb - 1] + g_bsum[nb - 1];
}

__global__ __launch_bounds__(256) void scatter_kernel(const int* __restrict__ w, int E)
{
    int is64 = block_probe_is64(w, E);
    int e = blockIdx.x * blockDim.x + threadIdx.x;
    if (e >= E) return;
    int src = load_idx(w, e, is64);
    int dst = load_idx(w, E + e, is64);
    int pos = atomicAdd(&g_cursor[src], 1);
    g_col[pos] = dst;
}

// ---------------------------------------------------------------
// layer-1 attention + aggregation + ELU (warp per node, 4 heads)
// single LDG.128/lane feature gather; 4-edge unroll.
// ---------------------------------------------------------------
__device__ __forceinline__ float sel4(float4 v, int q)
{
    float r = v.x;
    r = (q == 1) ? v.y : r;
    r = (q == 2) ? v.z : r;
    r = (q == 3) ? v.w : r;
    return r;
}

__device__ __forceinline__ void acc_f4(float2* acc, float pm, float4 hv)
{
    __half2 q0 = *(__half2*)&hv.x;
    __half2 q1 = *(__half2*)&hv.y;
    __half2 q2 = *(__half2*)&hv.z;
    __half2 q3 = *(__half2*)&hv.w;
    float2 f0 = __half22float2(q0);
    float2 f1 = __half22float2(q1);
    float2 f2 = __half22float2(q2);
    float2 f3 = __half22float2(q3);
    acc[0].x += pm * f0.x; acc[0].y += pm * f0.y;
    acc[1].x += pm * f1.x; acc[1].y += pm * f1.y;
    acc[2].x += pm * f2.x; acc[2].y += pm * f2.y;
    acc[3].x += pm * f3.x; acc[3].y += pm * f3.y;
}

__global__ __launch_bounds__(256) void agg_heads(int N)
{
    int warp = (blockIdx.x * blockDim.x + threadIdx.x) >> 5;
    int lane = threadIdx.x & 31;
    if (warp >= N) return;

    int e0 = g_rowptr[warp];
    int e1 = g_rowptr[warp + 1];
    int hq = lane & 3;                 // head this lane scores
    int myhead = lane >> 3;            // head this lane accumulates
    float4 s1v = *(const float4*)&g_s1h[warp * 4];
    float s1q = sel4(s1v, hq);

    float lloc = 0.f;
    float2 acc[4];
#pragma unroll
    for (int j = 0; j < 4; j++) acc[j] = make_float2(0.f, 0.f);

    int e = e0;
    for (; e + 4 <= e1; e += 4) {
        int d0 = g_col[e], d1 = g_col[e + 1], d2 = g_col[e + 2], d3 = g_col[e + 3];
        float4 s2v0 = *(const float4*)&g_s2h[d0 * 4];
        float4 s2v1 = *(const float4*)&g_s2h[d1 * 4];
        float4 s2v2 = *(const float4*)&g_s2h[d2 * 4];
        float4 s2v3 = *(const float4*)&g_s2h[d3 * 4];
        float4 h0 = ((const float4*)(g_H1h + (size_t)d0 * 128))[lane];
        float4 h1 = ((const float4*)(g_H1h + (size_t)d1 * 128))[lane];
        float4 h2 = ((const float4*)(g_H1h + (size_t)d2 * 128))[lane];
        float4 h3 = ((const float4*)(g_H1h + (size_t)d3 * 128))[lane];

        float s, p0, p1, p2, p3;
        s = s1q + sel4(s2v0, hq); s = -(s > 0.f ? s : ALPHA * s); p0 = __expf(s);
        s = s1q + sel4(s2v1, hq); s = -(s > 0.f ? s : ALPHA * s); p1 = __expf(s);
        s = s1q + sel4(s2v2, hq); s = -(s > 0.f ? s : ALPHA * s); p2 = __expf(s);
        s = s1q + sel4(s2v3, hq); s = -(s > 0.f ? s : ALPHA * s); p3 = __expf(s);
        lloc += p0 + p1 + p2 + p3;
        float pm0 = __shfl_sync(0xffffffffu, p0, myhead, 4);
        float pm1 = __shfl_sync(0xffffffffu, p1, myhead, 4);
        float pm2 = __shfl_sync(0xffffffffu, p2, myhead, 4);
        float pm3 = __shfl_sync(0xffffffffu, p3, myhead, 4);

        acc_f4(acc, pm0, h0);
        acc_f4(acc, pm1, h1);
        acc_f4(acc, pm2, h2);
        acc_f4(acc, pm3, h3);
    }
    for (; e < e1; e++) {
        int da = g_col[e];
        float4 s2a = *(const float4*)&g_s2h[da * 4];
        float4 ha = ((const float4*)(g_H1h + (size_t)da * 128))[lane];
        float sva = s1q + sel4(s2a, hq);
        float sca = -(sva > 0.f ? sva : ALPHA * sva);
        float pa = __expf(sca);
        lloc += pa;
        float pma = __shfl_sync(0xffffffffu, pa, myhead, 4);
        acc_f4(acc, pma, ha);
    }

    float lh = __shfl_sync(0xffffffffu, lloc, myhead, 4);
    float inv = (e1 > e0) ? 1.f / lh : 0.f;

    float o[8];
#pragma unroll
    for (int j = 0; j < 4; j++) {
        o[2 * j]     = acc[j].x * inv;
        o[2 * j + 1] = acc[j].y * inv;
    }
#pragma unroll
    for (int j = 0; j < 8; j++)
        o[j] = (o[j] > 0.f) ? o[j] : (__expf(o[j]) - 1.f);   // ELU

    __half2 oh[4];
#pragma unroll
    for (int j = 0; j < 4; j++)
        oh[j] = __floats2half2_rn(o[2 * j], o[2 * j + 1]);
    __half2* op = g_hcat16 + (size_t)warp * 128 + myhead * 32 + 4 * (lane & 7);
    op[0] = oh[0]; op[1] = oh[1]; op[2] = oh[2]; op[3] = oh[3];
}

// ---------------------------------------------------------------
// output-layer aggregation (warp per node, dim 64), 4-edge unroll
// ---------------------------------------------------------------
__global__ __launch_bounds__(256) void agg_out(float* __restrict__ out, int N)
{
    int warp = (blockIdx.x * blockDim.x + threadIdx.x) >> 5;
    int lane = threadIdx.x & 31;
    if (warp >= N) return;

    int e0 = g_rowptr[warp];
    int e1 = g_rowptr[warp + 1];
    float s1 = g_s1o[warp];

    float l = 0.f;
    float2 acc = make_float2(0.f, 0.f);

    int e = e0;
    for (; e + 4 <= e1; e += 4) {
        int d0 = g_col[e], d1i = g_col[e + 1], d2i = g_col[e + 2], d3i = g_col[e + 3];
        float t0 = g_s2o[d0], t1 = g_s2o[d1i], t2 = g_s2o[d2i], t3 = g_s2o[d3i];
        float2 v0 = __half22float2(g_H2h[(size_t)d0 * 32 + lane]);
        float2 v1 = __half22float2(g_H2h[(size_t)d1i * 32 + lane]);
        float2 v2 = __half22float2(g_H2h[(size_t)d2i * 32 + lane]);
        float2 v3 = __half22float2(g_H2h[(size_t)d3i * 32 + lane]);

        float s;
        s = s1 + t0; s = -(s > 0.f ? s : ALPHA * s); float p0 = __expf(s);
        s = s1 + t1; s = -(s > 0.f ? s : ALPHA * s); float p1 = __expf(s);
        s = s1 + t2; s = -(s > 0.f ? s : ALPHA * s); float p2 = __expf(s);
        s = s1 + t3; s = -(s > 0.f ? s : ALPHA * s); float p3 = __expf(s);
        l += p0 + p1 + p2 + p3;
        acc.x += p0 * v0.x + p1 * v1.x + p2 * v2.x + p3 * v3.x;
        acc.y += p0 * v0.y + p1 * v1.y + p2 * v2.y + p3 * v3.y;
    }
    for (; e < e1; e++) {
        int da = g_col[e];
        float s2a = g_s2o[da];
        float2 va = __half22float2(g_H2h[(size_t)da * 32 + lane]);
        float s = s1 + s2a;
        s = -(s > 0.f ? s : ALPHA * s);
        float pa = __expf(s);
        l += pa;
        acc.x += pa * va.x;
        acc.y += pa * va.y;
    }

    float va = 0.f, vb = 0.f;
    if (e1 > e0) {
        float inv = 1.f / l;
        va = acc.x * inv;
        vb = acc.y * inv;
    }
    *(float2*)(out + (size_t)warp * 64 + 2 * lane) = make_float2(va, vb);
}

// ---------------------------------------------------------------
extern "C" void kernel_launch(void* const* d_in, const int* in_sizes, int n_in,
                              void* d_out, int out_size)
{
    const float* x          = (const float*)d_in[0];
    const int*   ei_w       = (const int*)d_in[1];
    const float* W_heads    = (const float*)d_in[2];
    const float* attn_heads = (const float*)d_in[3];
    const float* W_out      = (const float*)d_in[4];
    const float* attn_out   = (const float*)d_in[5];
    float* out = (float*)d_out;

    int N = in_sizes[0] / 128;
    int E = in_sizes[1] / 2;

    int nodeWarpBlocks = (N + 7) / 8;
    int edgeBlocks = (E + 255) / 256;
    int scanBlocks = (N + 1023) / 1024;

    // one-time setup (first call is NOT under capture)
    static cudaStream_t sSide = nullptr;
    static cudaEvent_t evFork = nullptr, evJoin = nullptr;
    if (!sSide) {
        cudaStreamCreateWithFlags(&sSide, cudaStreamNonBlocking);
        cudaEventCreateWithFlags(&evFork, cudaEventDisableTiming);
        cudaEventCreateWithFlags(&evJoin, cudaEventDisableTiming);
        cudaFuncSetAttribute(h16_gemm, cudaFuncAttributeMaxDynamicSharedMemorySize, GEMM_SMEM);
    }

    // fork: CSR chain on side stream, GEMM1 on main stream
    cudaEventRecord(evFork, 0);
    cudaStreamWaitEvent(sSide, evFork, 0);

    hist_kernel<<<edgeBlocks, 256, 0, sSide>>>(ei_w, E);     // 1
    scan_p1<<<scanBlocks, 1024, 0, sSide>>>(N);              // 2
    scan_p3<<<scanBlocks, 1024, 0, sSide>>>(scanBlocks, N);  // 3

    // GEMM1 (+ fused svec + fp16 mirror): 4 head tiles — launch 4 (ncu slot)
    dim3 g1((N + 255) / 256, 4);
    h16_gemm<<<g1, 256, GEMM_SMEM>>>(x, 128, W_heads, attn_heads, 0, N, 128);

    scatter_kernel<<<edgeBlocks, 256, 0, sSide>>>(ei_w, E);  // 5
    cudaEventRecord(evJoin, sSide);

    cudaStreamWaitEvent(0, evJoin, 0);

    // layer-1 softmax+aggregate+ELU -> g_hcat16 (1 warp/node, float4 gather)
    agg_heads<<<nodeWarpBlocks, 256>>>(N);

    // GEMM2 (+ fused svec_out + fp16 mirror)
    dim3 g2((N + 255) / 256, 1);
    h16_gemm<<<g2, 256, GEMM_SMEM>>>(nullptr, 0, W_out, attn_out, 1, N, 256);

    // final aggregation
    agg_out<<<nodeWarpBlocks, 256>>>(out, N);
}

// round 13
// speedup vs baseline: 1.2199x; 1.0919x over previous
#include <cuda_runtime.h>
#include <cuda_fp16.h>
#include <math.h>

#define NMAX 50000
#define EMAX 800000
#define ALPHA 0.01f

// ---- static scratch (no allocations allowed) ----
__device__ __half2 g_H1h[(size_t)NMAX * 128]; // layer-1 features fp16, head-major (256 halves/row)
__device__ __half2 g_H2h[(size_t)NMAX * 32];  // layer-2 features fp16 (64 halves/row)
__device__ __half2 g_hcat16[(size_t)NMAX * 128]; // elu(attn out) fp16, layer-2 input
__device__ float g_s1h[NMAX * 4];
__device__ float g_s2h[NMAX * 4];
__device__ float g_s1o[NMAX];
__device__ float g_s2o[NMAX];
__device__ int   g_count[NMAX];               // .bss zero-init; scan_p1 re-zeroes each call
__device__ int   g_rowptr[NMAX + 1];
__device__ int   g_cursor[NMAX];
__device__ int   g_col[EMAX];
__device__ int   g_bsum[64];

// ---------------------------------------------------------------
__device__ __forceinline__ int block_probe_is64(const int* __restrict__ w, int E)
{
    int t = threadIdx.x;
    int nElem = (E < 128) ? E : 128;
    int ok = 1;
    if (t < nElem) ok = (w[2 * t + 1] == 0);
    return __syncthreads_and(ok);
}

__device__ __forceinline__ int load_idx(const int* __restrict__ w, int pos, int is64)
{
    return is64 ? w[2 * pos] : w[pos];
}

// ---------------------------------------------------------------
// fp16 tensor-core GEMM (m16n8k16, fp32 accum), 256x64 block tile,
// warp tile 32x64, ldmatrix.x4 smem reads.
// layer 0: heads looped INSIDE the block (A staged once, B per head).
// B converted fp32->fp16 + transposed during staging (STS.128,
// conflict-free). Fused epilogue per head: fp16 mirror + score dots.
// ---------------------------------------------------------------
__device__ __forceinline__ void mma16816(
    float* d, unsigned a0, unsigned a1, unsigned a2, unsigned a3,
    unsigned b0, unsigned b1)
{
    asm volatile(
        "mma.sync.aligned.m16n8k16.row.col.f32.f16.f16.f32 "
        "{%0,%1,%2,%3}, {%4,%5,%6,%7}, {%8,%9}, {%0,%1,%2,%3};\n"
        : "+f"(d[0]), "+f"(d[1]), "+f"(d[2]), "+f"(d[3])
        : "r"(a0), "r"(a1), "r"(a2), "r"(a3), "r"(b0), "r"(b1));
}

#define LDSM4(r0, r1, r2, r3, addr) \
    asm volatile("ldmatrix.sync.aligned.m8n8.x4.shared.b16 {%0,%1,%2,%3}, [%4];" \
        : "=r"(r0), "=r"(r1), "=r"(r2), "=r"(r3) : "r"(addr))

#define ROWW 68                                  // smem words per row (136 halves)
#define GEMM_SMEM ((64 * ROWW + 256 * ROWW) * 4) // B + A = 87040 B

__global__ __launch_bounds__(256, 2) void h16_gemm(
    const float* __restrict__ A32, int lda,
    const float* __restrict__ W32,
    const float* __restrict__ attn, int layer, int M, int K)
{
    extern __shared__ unsigned dsm[];
    unsigned* Bs = dsm;                    // [64][ROWW]
    unsigned* As = dsm + 64 * ROWW;        // [256][ROWW]

    const unsigned* A16 = (const unsigned*)g_hcat16;      // used when A32==null
    const int ldaW = 128;

    int row0 = blockIdx.x * 256;

    int tid = threadIdx.x;
    int lane = tid & 31, w = tid >> 5;
    int gid = lane >> 2, tig = lane & 3;

    // ldmatrix per-lane base addresses (bytes, shared space)
    unsigned smemB = (unsigned)__cvta_generic_to_shared(dsm);
    int aRow = w * 32 + (lane & 15);
    int aK = (lane & 16) ? 4 : 0;
    unsigned addrA0 = smemB + (unsigned)(64 * ROWW + aRow * ROWW + aK) * 4;
    unsigned addrA1 = addrA0 + 16 * ROWW * 4;
    int bRow = (lane & 7) + ((lane & 16) ? 8 : 0);
    int bK = (lane & 8) ? 4 : 0;
    unsigned addrB = smemB + (unsigned)(bRow * ROWW + bK) * 4;

    int rb = row0 + w * 32 + gid;
    int rows[4] = {rb, rb + 8, rb + 16, rb + 24};

    int nh = (layer == 0) ? 4 : 1;

    for (int head = 0; head < nh; head++) {
        const float* Bsrc = (layer == 0) ? W32 + (size_t)head * 8192 : W32;

        float acc0[8][4], acc1[8][4];
#pragma unroll
        for (int i = 0; i < 8; i++)
#pragma unroll
            for (int j = 0; j < 4; j++) { acc0[i][j] = 0.f; acc1[i][j] = 0.f; }

        for (int kc = 0; kc < K; kc += 128) {
            if (head || kc) __syncthreads();   // protect Bs (and As) reuse

            // stage B chunk [64 n][128 k] from fp32 [k][64 n]:
            // thread owns (n, 8-k group): 8 coalesced LDG.32 -> 1 STS.128
#pragma unroll
            for (int i = 0; i < 4; i++) {
                int t4 = tid + i * 256;        // 0..1023
                int n = t4 & 63, kg = t4 >> 6; // kg 0..15
                const float* src = Bsrc + (size_t)(kc + kg * 8) * 64 + n;
                __half2 h01 = __floats2half2_rn(src[0],   src[64]);
                __half2 h23 = __floats2half2_rn(src[128], src[192]);
                __half2 h45 = __floats2half2_rn(src[256], src[320]);
                __half2 h67 = __floats2half2_rn(src[384], src[448]);
                uint4 v = make_uint4(*(unsigned*)&h01, *(unsigned*)&h23,
                                     *(unsigned*)&h45, *(unsigned*)&h67);
                *(uint4*)((__half*)Bs + n * (ROWW * 2) + kg * 8) = v;
            }

            // stage A chunk once (head 0 covers all heads for layer 0)
            if (head == 0) {
                if (A32) {
#pragma unroll
                    for (int i = 0; i < 32; i++) {
                        int u = tid + i * 256;
                        int row = u >> 5, c4 = u & 31;
                        float4 av = make_float4(0.f, 0.f, 0.f, 0.f);
                        if (row0 + row < M)
                            av = *(const float4*)(A32 + (size_t)(row0 + row) * lda + kc + c4 * 4);
                        __half2 lo = __floats2half2_rn(av.x, av.y);
                        __half2 hi = __floats2half2_rn(av.z, av.w);
                        *(uint2*)&As[row * ROWW + 2 * c4] =
                            make_uint2(*(unsigned*)&lo, *(unsigned*)&hi);
                    }
                } else {
#pragma unroll
                    for (int i = 0; i < 32; i++) {
                        int u = tid + i * 256;
                        int row = u >> 5, w2 = u & 31;
                        uint2 v = make_uint2(0u, 0u);
                        if (row0 + row < M)
                            v = *(const uint2*)(A16 + (size_t)(row0 + row) * ldaW + (kc >> 1) + 2 * w2);
                        *(uint2*)&As[row * ROWW + 2 * w2] = v;
                    }
                }
            }
            __syncthreads();

#pragma unroll
            for (int s = 0; s < 8; s++) {          // 8 k16 steps per 128-half chunk
                unsigned off = s * 32;             // 8 words = 32 bytes per step
                unsigned a00, a01, a02, a03, a10, a11, a12, a13;
                LDSM4(a00, a01, a02, a03, addrA0 + off);
                LDSM4(a10, a11, a12, a13, addrA1 + off);
#pragma unroll
                for (int np = 0; np < 4; np++) {
                    unsigned b0, b1, b2, b3;
                    LDSM4(b0, b1, b2, b3, addrB + off + np * (16 * ROWW * 4));
                    mma16816(acc0[2 * np],     a00, a01, a02, a03, b0, b1);
                    mma16816(acc1[2 * np],     a10, a11, a12, a13, b0, b1);
                    mma16816(acc0[2 * np + 1], a00, a01, a02, a03, b2, b3);
                    mma16816(acc1[2 * np + 1], a10, a11, a12, a13, b2, b3);
                }
            }
        }

        // ---- fused epilogue (per head) ----
        __half2* Hh2;
        int ldH2, colBase2, sStride, sOff;
        float *s1g, *s2g;
        const float* a1;
        if (layer == 0) {
            Hh2 = g_H1h; ldH2 = 128; colBase2 = head * 32;
            sStride = 4; sOff = head; s1g = g_s1h; s2g = g_s2h;
            a1 = attn + head * 128;
        } else {
            Hh2 = g_H2h; ldH2 = 32; colBase2 = 0;
            sStride = 1; sOff = 0; s1g = g_s1o; s2g = g_s2o;
            a1 = attn;
        }
        const float* a2v = a1 + 64;

        float d1[4] = {0.f, 0.f, 0.f, 0.f};
        float d2[4] = {0.f, 0.f, 0.f, 0.f};
#pragma unroll
        for (int n0 = 0; n0 < 8; n0++) {
            int c0 = n0 * 8 + 2 * tig;
            float w10 = __ldg(a1 + c0), w11 = __ldg(a1 + c0 + 1);
            float w20 = __ldg(a2v + c0), w21 = __ldg(a2v + c0 + 1);
            d1[0] += acc0[n0][0] * w10 + acc0[n0][1] * w11;
            d2[0] += acc0[n0][0] * w20 + acc0[n0][1] * w21;
            d1[1] += acc0[n0][2] * w10 + acc0[n0][3] * w11;
            d2[1] += acc0[n0][2] * w20 + acc0[n0][3] * w21;
            d1[2] += acc1[n0][0] * w10 + acc1[n0][1] * w11;
            d2[2] += acc1[n0][0] * w20 + acc1[n0][1] * w21;
            d1[3] += acc1[n0][2] * w10 + acc1[n0][3] * w11;
            d2[3] += acc1[n0][2] * w20 + acc1[n0][3] * w21;
        }
#pragma unroll
        for (int f = 0; f < 4; f++) {
#pragma unroll
            for (int off = 1; off < 4; off <<= 1) {
                d1[f] += __shfl_xor_sync(0xffffffffu, d1[f], off);
                d2[f] += __shfl_xor_sync(0xffffffffu, d2[f], off);
            }
        }
        if (tig == 0) {
#pragma unroll
            for (int f = 0; f < 4; f++) {
                if (rows[f] < M) {
                    s1g[rows[f] * sStride + sOff] = d1[f];
                    s2g[rows[f] * sStride + sOff] = d2[f];
                }
            }
        }

#pragma unroll
        for (int n0 = 0; n0 < 8; n0++) {
            int cc = colBase2 + n0 * 4 + tig;
            if (rows[0] < M)
                Hh2[(size_t)rows[0] * ldH2 + cc] = __floats2half2_rn(acc0[n0][0], acc0[n0][1]);
            if (rows[1] < M)
                Hh2[(size_t)rows[1] * ldH2 + cc] = __floats2half2_rn(acc0[n0][2], acc0[n0][3]);
            if (rows[2] < M)
                Hh2[(size_t)rows[2] * ldH2 + cc] = __floats2half2_rn(acc1[n0][0], acc1[n0][1]);
            if (rows[3] < M)
                Hh2[(size_t)rows[3] * ldH2 + cc] = __floats2half2_rn(acc1[n0][2], acc1[n0][3]);
        }
    }
}

// ---------------------------------------------------------------
// CSR build
// ---------------------------------------------------------------
__global__ __launch_bounds__(256) void hist_kernel(const int* __restrict__ w, int E)
{
    int is64 = block_probe_is64(w, E);
    int e = blockIdx.x * blockDim.x + threadIdx.x;
    if (e >= E) return;
    atomicAdd(&g_count[load_idx(w, e, is64)], 1);
}

__global__ __launch_bounds__(1024) void scan_p1(int n)
{
    __shared__ int wsum[32];
    int t = threadIdx.x;
    int i = blockIdx.x * 1024 + t;
    int v = (i < n) ? g_count[i] : 0;
    if (i < n) g_count[i] = 0;            // self-clear for next call
    int lane = t & 31, w = t >> 5;

    int x = v;
#pragma unroll
    for (int off = 1; off < 32; off <<= 1) {
        int y = __shfl_up_sync(0xffffffffu, x, off);
        if (lane >= off) x += y;
    }
    if (lane == 31) wsum[w] = x;
    __syncthreads();
    if (w == 0) {
        int z = wsum[lane];
#pragma unroll
        for (int off = 1; off < 32; off <<= 1) {
            int y = __shfl_up_sync(0xffffffffu, z, off);
            if (lane >= off) z += y;
        }
        wsum[lane] = z;
    }
    __syncthreads();
    int excl = x - v + (w > 0 ? wsum[w - 1] : 0);
    if (i < n) g_rowptr[i] = excl;
    if (t == 1023) g_bsum[blockIdx.x] = excl + v;
}

__global__ __launch_bounds__(1024) void scan_p3(int nb, int n)
{
    __shared__ int boff[64];
    int t = threadIdx.x;
    if (t < 64) {
        int v = (t < nb) ? g_bsum[t] : 0;
        int lane = t & 31;
        int x = v;
#pragma unroll
        for (int off = 1; off < 32; off <<= 1) {
            int y = __shfl_up_sync(0xffffffffu, x, off);
            if (lane >= off) x += y;
        }
        boff[t] = x - v;
    }
    __syncthreads();
    if (t >= 32 && t < 64)
        boff[t] += boff[31] + g_bsum[31];
    __syncthreads();

    int i = blockIdx.x * 1024 + t;
    if (i < n) {
        int val = g_rowptr[i] + boff[blockIdx.x];
        g_rowptr[i] = val;
        g_cursor[i] = val;
    }
    if (blockIdx.x == 0 && t == 0)
        g_rowptr[n] = boff[nb - 1] + g_bsum[nb - 1];
}

__global__ __launch_bounds__(256) void scatter_kernel(const int* __restrict__ w, int E)
{
    int is64 = block_probe_is64(w, E);
    int e = blockIdx.x * blockDim.x + threadIdx.x;
    if (e >= E) return;
    int src = load_idx(w, e, is64);
    int dst = load_idx(w, E + e, is64);
    int pos = atomicAdd(&g_cursor[src], 1);
    g_col[pos] = dst;
}

// ---------------------------------------------------------------
// layer-1 attention + aggregation + ELU (warp per node, 4 heads)
// single LDG.128/lane feature gather; 4-edge unroll.
// ---------------------------------------------------------------
__device__ __forceinline__ float sel4(float4 v, int q)
{
    float r = v.x;
    r = (q == 1) ? v.y : r;
    r = (q == 2) ? v.z : r;
    r = (q == 3) ? v.w : r;
    return r;
}

__device__ __forceinline__ void acc_f4(float2* acc, float pm, float4 hv)
{
    __half2 q0 = *(__half2*)&hv.x;
    __half2 q1 = *(__half2*)&hv.y;
    __half2 q2 = *(__half2*)&hv.z;
    __half2 q3 = *(__half2*)&hv.w;
    float2 f0 = __half22float2(q0);
    float2 f1 = __half22float2(q1);
    float2 f2 = __half22float2(q2);
    float2 f3 = __half22float2(q3);
    acc[0].x += pm * f0.x; acc[0].y += pm * f0.y;
    acc[1].x += pm * f1.x; acc[1].y += pm * f1.y;
    acc[2].x += pm * f2.x; acc[2].y += pm * f2.y;
    acc[3].x += pm * f3.x; acc[3].y += pm * f3.y;
}

__global__ __launch_bounds__(256) void agg_heads(int N)
{
    int warp = (blockIdx.x * blockDim.x + threadIdx.x) >> 5;
    int lane = threadIdx.x & 31;
    if (warp >= N) return;

    int e0 = g_rowptr[warp];
    int e1 = g_rowptr[warp + 1];
    int hq = lane & 3;                 // head this lane scores
    int myhead = lane >> 3;            // head this lane accumulates
    float4 s1v = *(const float4*)&g_s1h[warp * 4];
    float s1q = sel4(s1v, hq);

    float lloc = 0.f;
    float2 acc[4];
#pragma unroll
    for (int j = 0; j < 4; j++) acc[j] = make_float2(0.f, 0.f);

    int e = e0;
    for (; e + 4 <= e1; e += 4) {
        int d0 = g_col[e], d1 = g_col[e + 1], d2 = g_col[e + 2], d3 = g_col[e + 3];
        float4 s2v0 = *(const float4*)&g_s2h[d0 * 4];
        float4 s2v1 = *(const float4*)&g_s2h[d1 * 4];
        float4 s2v2 = *(const float4*)&g_s2h[d2 * 4];
        float4 s2v3 = *(const float4*)&g_s2h[d3 * 4];
        float4 h0 = ((const float4*)(g_H1h + (size_t)d0 * 128))[lane];
        float4 h1 = ((const float4*)(g_H1h + (size_t)d1 * 128))[lane];
        float4 h2 = ((const float4*)(g_H1h + (size_t)d2 * 128))[lane];
        float4 h3 = ((const float4*)(g_H1h + (size_t)d3 * 128))[lane];

        float s, p0, p1, p2, p3;
        s = s1q + sel4(s2v0, hq); s = -(s > 0.f ? s : ALPHA * s); p0 = __expf(s);
        s = s1q + sel4(s2v1, hq); s = -(s > 0.f ? s : ALPHA * s); p1 = __expf(s);
        s = s1q + sel4(s2v2, hq); s = -(s > 0.f ? s : ALPHA * s); p2 = __expf(s);
        s = s1q + sel4(s2v3, hq); s = -(s > 0.f ? s : ALPHA * s); p3 = __expf(s);
        lloc += p0 + p1 + p2 + p3;
        float pm0 = __shfl_sync(0xffffffffu, p0, myhead, 4);
        float pm1 = __shfl_sync(0xffffffffu, p1, myhead, 4);
        float pm2 = __shfl_sync(0xffffffffu, p2, myhead, 4);
        float pm3 = __shfl_sync(0xffffffffu, p3, myhead, 4);

        acc_f4(acc, pm0, h0);
        acc_f4(acc, pm1, h1);
        acc_f4(acc, pm2, h2);
        acc_f4(acc, pm3, h3);
    }
    for (; e < e1; e++) {
        int da = g_col[e];
        float4 s2a = *(const float4*)&g_s2h[da * 4];
        float4 ha = ((const float4*)(g_H1h + (size_t)da * 128))[lane];
        float sva = s1q + sel4(s2a, hq);
        float sca = -(sva > 0.f ? sva : ALPHA * sva);
        float pa = __expf(sca);
        lloc += pa;
        float pma = __shfl_sync(0xffffffffu, pa, myhead, 4);
        acc_f4(acc, pma, ha);
    }

    float lh = __shfl_sync(0xffffffffu, lloc, myhead, 4);
    float inv = (e1 > e0) ? 1.f / lh : 0.f;

    float o[8];
#pragma unroll
    for (int j = 0; j < 4; j++) {
        o[2 * j]     = acc[j].x * inv;
        o[2 * j + 1] = acc[j].y * inv;
    }
#pragma unroll
    for (int j = 0; j < 8; j++)
        o[j] = (o[j] > 0.f) ? o[j] : (__expf(o[j]) - 1.f);   // ELU

    __half2 oh[4];
#pragma unroll
    for (int j = 0; j < 4; j++)
        oh[j] = __floats2half2_rn(o[2 * j], o[2 * j + 1]);
    __half2* op = g_hcat16 + (size_t)warp * 128 + myhead * 32 + 4 * (lane & 7);
    op[0] = oh[0]; op[1] = oh[1]; op[2] = oh[2]; op[3] = oh[3];
}

// ---------------------------------------------------------------
// output-layer aggregation (warp per node, dim 64), 4-edge unroll
// ---------------------------------------------------------------
__global__ __launch_bounds__(256) void agg_out(float* __restrict__ out, int N)
{
    int warp = (blockIdx.x * blockDim.x + threadIdx.x) >> 5;
    int lane = threadIdx.x & 31;
    if (warp >= N) return;

    int e0 = g_rowptr[warp];
    int e1 = g_rowptr[warp + 1];
    float s1 = g_s1o[warp];

    float l = 0.f;
    float2 acc = make_float2(0.f, 0.f);

    int e = e0;
    for (; e + 4 <= e1; e += 4) {
        int d0 = g_col[e], d1i = g_col[e + 1], d2i = g_col[e + 2], d3i = g_col[e + 3];
        float t0 = g_s2o[d0], t1 = g_s2o[d1i], t2 = g_s2o[d2i], t3 = g_s2o[d3i];
        float2 v0 = __half22float2(g_H2h[(size_t)d0 * 32 + lane]);
        float2 v1 = __half22float2(g_H2h[(size_t)d1i * 32 + lane]);
        float2 v2 = __half22float2(g_H2h[(size_t)d2i * 32 + lane]);
        float2 v3 = __half22float2(g_H2h[(size_t)d3i * 32 + lane]);

        float s;
        s = s1 + t0; s = -(s > 0.f ? s : ALPHA * s); float p0 = __expf(s);
        s = s1 + t1; s = -(s > 0.f ? s : ALPHA * s); float p1 = __expf(s);
        s = s1 + t2; s = -(s > 0.f ? s : ALPHA * s); float p2 = __expf(s);
        s = s1 + t3; s = -(s > 0.f ? s : ALPHA * s); float p3 = __expf(s);
        l += p0 + p1 + p2 + p3;
        acc.x += p0 * v0.x + p1 * v1.x + p2 * v2.x + p3 * v3.x;
        acc.y += p0 * v0.y + p1 * v1.y + p2 * v2.y + p3 * v3.y;
    }
    for (; e < e1; e++) {
        int da = g_col[e];
        float s2a = g_s2o[da];
        float2 va = __half22float2(g_H2h[(size_t)da * 32 + lane]);
        float s = s1 + s2a;
        s = -(s > 0.f ? s : ALPHA * s);
        float pa = __expf(s);
        l += pa;
        acc.x += pa * va.x;
        acc.y += pa * va.y;
    }

    float va = 0.f, vb = 0.f;
    if (e1 > e0) {
        float inv = 1.f / l;
        va = acc.x * inv;
        vb = acc.y * inv;
    }
    *(float2*)(out + (size_t)warp * 64 + 2 * lane) = make_float2(va, vb);
}

// ---------------------------------------------------------------
extern "C" void kernel_launch(void* const* d_in, const int* in_sizes, int n_in,
                              void* d_out, int out_size)
{
    const float* x          = (const float*)d_in[0];
    const int*   ei_w       = (const int*)d_in[1];
    const float* W_heads    = (const float*)d_in[2];
    const float* attn_heads = (const float*)d_in[3];
    const float* W_out      = (const float*)d_in[4];
    const float* attn_out   = (const float*)d_in[5];
    float* out = (float*)d_out;

    int N = in_sizes[0] / 128;
    int E = in_sizes[1] / 2;

    int nodeWarpBlocks = (N + 7) / 8;
    int edgeBlocks = (E + 255) / 256;
    int scanBlocks = (N + 1023) / 1024;

    // one-time setup (first call is NOT under capture)
    static cudaStream_t sSide = nullptr;
    static cudaEvent_t evFork = nullptr, evJoin = nullptr;
    if (!sSide) {
        cudaStreamCreateWithFlags(&sSide, cudaStreamNonBlocking);
        cudaEventCreateWithFlags(&evFork, cudaEventDisableTiming);
        cudaEventCreateWithFlags(&evJoin, cudaEventDisableTiming);
        cudaFuncSetAttribute(h16_gemm, cudaFuncAttributeMaxDynamicSharedMemorySize, GEMM_SMEM);
    }

    // fork: CSR chain on side stream, GEMM1 on main stream
    cudaEventRecord(evFork, 0);
    cudaStreamWaitEvent(sSide, evFork, 0);

    hist_kernel<<<edgeBlocks, 256, 0, sSide>>>(ei_w, E);     // 1
    scan_p1<<<scanBlocks, 1024, 0, sSide>>>(N);              // 2
    scan_p3<<<scanBlocks, 1024, 0, sSide>>>(scanBlocks, N);  // 3

    // GEMM1 (all 4 heads in-block, fused svec + fp16 mirror) — launch 4 (ncu slot)
    dim3 g1((N + 255) / 256, 1);
    h16_gemm<<<g1, 256, GEMM_SMEM>>>(x, 128, W_heads, attn_heads, 0, N, 128);

    scatter_kernel<<<edgeBlocks, 256, 0, sSide>>>(ei_w, E);  // 5
    cudaEventRecord(evJoin, sSide);

    cudaStreamWaitEvent(0, evJoin, 0);

    // layer-1 softmax+aggregate+ELU -> g_hcat16 (1 warp/node, float4 gather)
    agg_heads<<<nodeWarpBlocks, 256>>>(N);

    // GEMM2 (+ fused svec_out + fp16 mirror)
    dim3 g2((N + 255) / 256, 1);
    h16_gemm<<<g2, 256, GEMM_SMEM>>>(nullptr, 0, W_out, attn_out, 1, N, 256);

    // final aggregation
    agg_out<<<nodeWarpBlocks, 256>>>(out, N);
}

// round 14
// speedup vs baseline: 1.2347x; 1.0122x over previous
#include <cuda_runtime.h>
#include <cuda_fp16.h>
#include <math.h>

#define NMAX 50000
#define EMAX 800000
#define ALPHA 0.01f

// ---- static scratch (no allocations allowed) ----
__device__ __half2 g_H1h[(size_t)NMAX * 128]; // layer-1 features fp16, head-major (256 halves/row)
__device__ __half2 g_H2h[(size_t)NMAX * 32];  // layer-2 features fp16 (64 halves/row)
__device__ __half2 g_hcat16[(size_t)NMAX * 128]; // elu(attn out) fp16, layer-2 input
__device__ float g_s1h[NMAX * 4];
__device__ float g_s2h[NMAX * 4];
__device__ float g_s1o[NMAX];
__device__ float g_s2o[NMAX];
__device__ int   g_count[NMAX];               // .bss zero-init; scan_p1 re-zeroes each call
__device__ int   g_rowptr[NMAX + 1];
__device__ int   g_cursor[NMAX];
__device__ int   g_col[EMAX];
__device__ int   g_bsum[64];

// ---------------------------------------------------------------
__device__ __forceinline__ int block_probe_is64(const int* __restrict__ w, int E)
{
    int t = threadIdx.x;
    int nElem = (E < 128) ? E : 128;
    int ok = 1;
    if (t < nElem) ok = (w[2 * t + 1] == 0);
    return __syncthreads_and(ok);
}

__device__ __forceinline__ int load_idx(const int* __restrict__ w, int pos, int is64)
{
    return is64 ? w[2 * pos] : w[pos];
}

// ---------------------------------------------------------------
// fp16 tensor-core GEMM (m16n8k16, fp32 accum), 128x64 block tile,
// warp tile 32x32 (8 warps = 4 row-groups x 2 col-groups), 3 blocks/SM.
// layer 0: heads looped INSIDE the block (A staged once, B per head).
// Score dots computed as per-warp partials over 32 cols, combined via smem.
// ---------------------------------------------------------------
__device__ __forceinline__ void mma16816(
    float* d, unsigned a0, unsigned a1, unsigned a2, unsigned a3,
    unsigned b0, unsigned b1)
{
    asm volatile(
        "mma.sync.aligned.m16n8k16.row.col.f32.f16.f16.f32 "
        "{%0,%1,%2,%3}, {%4,%5,%6,%7}, {%8,%9}, {%0,%1,%2,%3};\n"
        : "+f"(d[0]), "+f"(d[1]), "+f"(d[2]), "+f"(d[3])
        : "r"(a0), "r"(a1), "r"(a2), "r"(a3), "r"(b0), "r"(b1));
}

#define LDSM4(r0, r1, r2, r3, addr) \
    asm volatile("ldmatrix.sync.aligned.m8n8.x4.shared.b16 {%0,%1,%2,%3}, [%4];" \
        : "=r"(r0), "=r"(r1), "=r"(r2), "=r"(r3) : "r"(addr))

#define ROWW 68                                   // smem words per row (136 halves)
#define GEMM_SMEM ((64 * ROWW + 128 * ROWW) * 4 + 2048) // B + A + score partials

__global__ __launch_bounds__(256, 3) void h16_gemm(
    const float* __restrict__ A32, int lda,
    const float* __restrict__ W32,
    const float* __restrict__ attn, int layer, int M, int K)
{
    extern __shared__ unsigned dsm[];
    unsigned* Bs = dsm;                    // [64][ROWW]
    unsigned* As = dsm + 64 * ROWW;        // [128][ROWW]
    float* sp = (float*)(dsm + 192 * ROWW);// [8][64] score-dot partials

    const unsigned* A16 = (const unsigned*)g_hcat16;      // used when A32==null
    const int ldaW = 128;

    int row0 = blockIdx.x * 128;

    int tid = threadIdx.x;
    int lane = tid & 31, w = tid >> 5;
    int r = w >> 1;                 // row group 0..3 (32 rows each)
    int cg = w & 1;                 // col group 0..1 (32 cols each)
    int gid = lane >> 2, tig = lane & 3;

    // ldmatrix per-lane base addresses (bytes, shared space)
    unsigned smemB = (unsigned)__cvta_generic_to_shared(dsm);
    int aRow = r * 32 + (lane & 15);
    int aK = (lane & 16) ? 4 : 0;
    unsigned addrA0 = smemB + (unsigned)(64 * ROWW + aRow * ROWW + aK) * 4;
    unsigned addrA1 = addrA0 + 16 * ROWW * 4;
    int bRow = (lane & 7) + ((lane & 16) ? 8 : 0) + cg * 32;
    int bK = (lane & 8) ? 4 : 0;
    unsigned addrB = smemB + (unsigned)(bRow * ROWW + bK) * 4;

    int rb = row0 + r * 32 + gid;
    int rows[4] = {rb, rb + 8, rb + 16, rb + 24};

    int nh = (layer == 0) ? 4 : 1;

    for (int head = 0; head < nh; head++) {
        const float* Bsrc = (layer == 0) ? W32 + (size_t)head * 8192 : W32;

        float acc0[4][4], acc1[4][4];
#pragma unroll
        for (int i = 0; i < 4; i++)
#pragma unroll
            for (int j = 0; j < 4; j++) { acc0[i][j] = 0.f; acc1[i][j] = 0.f; }

        for (int kc = 0; kc < K; kc += 128) {
            if (head || kc) __syncthreads();   // protect Bs/As/sp reuse

            // stage B chunk [64 n][128 k] from fp32 [k][64 n]:
            // thread owns (n, 8-k group): 8 coalesced LDG.32 -> 1 STS.128
#pragma unroll
            for (int i = 0; i < 4; i++) {
                int t4 = tid + i * 256;        // 0..1023
                int n = t4 & 63, kg = t4 >> 6; // kg 0..15
                const float* src = Bsrc + (size_t)(kc + kg * 8) * 64 + n;
                __half2 h01 = __floats2half2_rn(src[0],   src[64]);
                __half2 h23 = __floats2half2_rn(src[128], src[192]);
                __half2 h45 = __floats2half2_rn(src[256], src[320]);
                __half2 h67 = __floats2half2_rn(src[384], src[448]);
                uint4 v = make_uint4(*(unsigned*)&h01, *(unsigned*)&h23,
                                     *(unsigned*)&h45, *(unsigned*)&h67);
                *(uint4*)((__half*)Bs + n * (ROWW * 2) + kg * 8) = v;
            }

            // stage A chunk once (head 0 covers all heads for layer 0)
            if (head == 0) {
                if (A32) {
#pragma unroll
                    for (int i = 0; i < 16; i++) {
                        int u = tid + i * 256;
                        int row = u >> 5, c4 = u & 31;
                        float4 av = make_float4(0.f, 0.f, 0.f, 0.f);
                        if (row0 + row < M)
                            av = *(const float4*)(A32 + (size_t)(row0 + row) * lda + kc + c4 * 4);
                        __half2 lo = __floats2half2_rn(av.x, av.y);
                        __half2 hi = __floats2half2_rn(av.z, av.w);
                        *(uint2*)&As[row * ROWW + 2 * c4] =
                            make_uint2(*(unsigned*)&lo, *(unsigned*)&hi);
                    }
                } else {
#pragma unroll
                    for (int i = 0; i < 16; i++) {
                        int u = tid + i * 256;
                        int row = u >> 5, w2 = u & 31;
                        uint2 v = make_uint2(0u, 0u);
                        if (row0 + row < M)
                            v = *(const uint2*)(A16 + (size_t)(row0 + row) * ldaW + (kc >> 1) + 2 * w2);
                        *(uint2*)&As[row * ROWW + 2 * w2] = v;
                    }
                }
            }
            __syncthreads();

#pragma unroll
            for (int s = 0; s < 8; s++) {          // 8 k16 steps per 128-half chunk
                unsigned off = s * 32;             // 8 words = 32 bytes per step
                unsigned a00, a01, a02, a03, a10, a11, a12, a13;
                LDSM4(a00, a01, a02, a03, addrA0 + off);
                LDSM4(a10, a11, a12, a13, addrA1 + off);
#pragma unroll
                for (int np = 0; np < 2; np++) {
                    unsigned b0, b1, b2, b3;
                    LDSM4(b0, b1, b2, b3, addrB + off + np * (16 * ROWW * 4));
                    mma16816(acc0[2 * np],     a00, a01, a02, a03, b0, b1);
                    mma16816(acc1[2 * np],     a10, a11, a12, a13, b0, b1);
                    mma16816(acc0[2 * np + 1], a00, a01, a02, a03, b2, b3);
                    mma16816(acc1[2 * np + 1], a10, a11, a12, a13, b2, b3);
                }
            }
        }

        // ---- fused epilogue (per head) ----
        __half2* Hh2;
        int ldH2, colBase2, sStride, sOff;
        float *s1g, *s2g;
        const float* a1;
        if (layer == 0) {
            Hh2 = g_H1h; ldH2 = 128; colBase2 = head * 32 + cg * 16;
            sStride = 4; sOff = head; s1g = g_s1h; s2g = g_s2h;
            a1 = attn + head * 128;
        } else {
            Hh2 = g_H2h; ldH2 = 32; colBase2 = cg * 16;
            sStride = 1; sOff = 0; s1g = g_s1o; s2g = g_s2o;
            a1 = attn;
        }
        const float* a2v = a1 + 64;

        // partial score dots over this warp's 32 cols
        float d1[4] = {0.f, 0.f, 0.f, 0.f};
        float d2[4] = {0.f, 0.f, 0.f, 0.f};
#pragma unroll
        for (int n0 = 0; n0 < 4; n0++) {
            int c0 = cg * 32 + n0 * 8 + 2 * tig;
            float w10 = __ldg(a1 + c0), w11 = __ldg(a1 + c0 + 1);
            float w20 = __ldg(a2v + c0), w21 = __ldg(a2v + c0 + 1);
            d1[0] += acc0[n0][0] * w10 + acc0[n0][1] * w11;
            d2[0] += acc0[n0][0] * w20 + acc0[n0][1] * w21;
            d1[1] += acc0[n0][2] * w10 + acc0[n0][3] * w11;
            d2[1] += acc0[n0][2] * w20 + acc0[n0][3] * w21;
            d1[2] += acc1[n0][0] * w10 + acc1[n0][1] * w11;
            d2[2] += acc1[n0][0] * w20 + acc1[n0][1] * w21;
            d1[3] += acc1[n0][2] * w10 + acc1[n0][3] * w11;
            d2[3] += acc1[n0][2] * w20 + acc1[n0][3] * w21;
        }
#pragma unroll
        for (int f = 0; f < 4; f++) {
#pragma unroll
            for (int off = 1; off < 4; off <<= 1) {
                d1[f] += __shfl_xor_sync(0xffffffffu, d1[f], off);
                d2[f] += __shfl_xor_sync(0xffffffffu, d2[f], off);
            }
        }
        if (tig == 0) {
#pragma unroll
            for (int f = 0; f < 4; f++) {
                int rl = f * 8 + gid;          // local row 0..31
                sp[w * 64 + rl * 2]     = d1[f];
                sp[w * 64 + rl * 2 + 1] = d2[f];
            }
        }
        __syncthreads();
        if (cg == 0) {                         // even warps combine col halves
            int rowg = row0 + r * 32 + lane;   // rl == lane
            float d1t = sp[w * 64 + lane * 2]     + sp[(w + 1) * 64 + lane * 2];
            float d2t = sp[w * 64 + lane * 2 + 1] + sp[(w + 1) * 64 + lane * 2 + 1];
            if (rowg < M) {
                s1g[rowg * sStride + sOff] = d1t;
                s2g[rowg * sStride + sOff] = d2t;
            }
        }

        // fp16 mirror writes (this warp's 32 cols x 32 rows)
#pragma unroll
        for (int n0 = 0; n0 < 4; n0++) {
            int cc = colBase2 + n0 * 4 + tig;
            if (rows[0] < M)
                Hh2[(size_t)rows[0] * ldH2 + cc] = __floats2half2_rn(acc0[n0][0], acc0[n0][1]);
            if (rows[1] < M)
                Hh2[(size_t)rows[1] * ldH2 + cc] = __floats2half2_rn(acc0[n0][2], acc0[n0][3]);
            if (rows[2] < M)
                Hh2[(size_t)rows[2] * ldH2 + cc] = __floats2half2_rn(acc1[n0][0], acc1[n0][1]);
            if (rows[3] < M)
                Hh2[(size_t)rows[3] * ldH2 + cc] = __floats2half2_rn(acc1[n0][2], acc1[n0][3]);
        }
    }
}

// ---------------------------------------------------------------
// CSR build
// ---------------------------------------------------------------
__global__ __launch_bounds__(256) void hist_kernel(const int* __restrict__ w, int E)
{
    int is64 = block_probe_is64(w, E);
    int e = blockIdx.x * blockDim.x + threadIdx.x;
    if (e >= E) return;
    atomicAdd(&g_count[load_idx(w, e, is64)], 1);
}

__global__ __launch_bounds__(1024) void scan_p1(int n)
{
    __shared__ int wsum[32];
    int t = threadIdx.x;
    int i = blockIdx.x * 1024 + t;
    int v = (i < n) ? g_count[i] : 0;
    if (i < n) g_count[i] = 0;            // self-clear for next call
    int lane = t & 31, w = t >> 5;

    int x = v;
#pragma unroll
    for (int off = 1; off < 32; off <<= 1) {
        int y = __shfl_up_sync(0xffffffffu, x, off);
        if (lane >= off) x += y;
    }
    if (lane == 31) wsum[w] = x;
    __syncthreads();
    if (w == 0) {
        int z = wsum[lane];
#pragma unroll
        for (int off = 1; off < 32; off <<= 1) {
            int y = __shfl_up_sync(0xffffffffu, z, off);
            if (lane >= off) z += y;
        }
        wsum[lane] = z;
    }
    __syncthreads();
    int excl = x - v + (w > 0 ? wsum[w - 1] : 0);
    if (i < n) g_rowptr[i] = excl;
    if (t == 1023) g_bsum[blockIdx.x] = excl + v;
}

__global__ __launch_bounds__(1024) void scan_p3(int nb, int n)
{
    __shared__ int boff[64];
    int t = threadIdx.x;
    if (t < 64) {
        int v = (t < nb) ? g_bsum[t] : 0;
        int lane = t & 31;
        int x = v;
#pragma unroll
        for (int off = 1; off < 32; off <<= 1) {
            int y = __shfl_up_sync(0xffffffffu, x, off);
            if (lane >= off) x += y;
        }
        boff[t] = x - v;
    }
    __syncthreads();
    if (t >= 32 && t < 64)
        boff[t] += boff[31] + g_bsum[31];
    __syncthreads();

    int i = blockIdx.x * 1024 + t;
    if (i < n) {
        int val = g_rowptr[i] + boff[blockIdx.x];
        g_rowptr[i] = val;
        g_cursor[i] = val;
    }
    if (blockIdx.x == 0 && t == 0)
        g_rowptr[n] = boff[nb - 1] + g_bsum[nb - 1];
}

__global__ __launch_bounds__(256) void scatter_kernel(const int* __restrict__ w, int E)
{
    int is64 = block_probe_is64(w, E);
    int e = blockIdx.x * blockDim.x + threadIdx.x;
    if (e >= E) return;
    int src = load_idx(w, e, is64);
    int dst = load_idx(w, E + e, is64);
    int pos = atomicAdd(&g_cursor[src], 1);
    g_col[pos] = dst;
}

// ---------------------------------------------------------------
// layer-1 attention + aggregation + ELU (warp per node, 4 heads)
// single LDG.128/lane feature gather; 4-edge unroll with col prefetch.
// ---------------------------------------------------------------
__device__ __forceinline__ float sel4(float4 v, int q)
{
    float r = v.x;
    r = (q == 1) ? v.y : r;
    r = (q == 2) ? v.z : r;
    r = (q == 3) ? v.w : r;
    return r;
}

__device__ __forceinline__ void acc_f4(float2* acc, float pm, float4 hv)
{
    __half2 q0 = *(__half2*)&hv.x;
    __half2 q1 = *(__half2*)&hv.y;
    __half2 q2 = *(__half2*)&hv.z;
    __half2 q3 = *(__half2*)&hv.w;
    float2 f0 = __half22float2(q0);
    float2 f1 = __half22float2(q1);
    float2 f2 = __half22float2(q2);
    float2 f3 = __half22float2(q3);
    acc[0].x += pm * f0.x; acc[0].y += pm * f0.y;
    acc[1].x += pm * f1.x; acc[1].y += pm * f1.y;
    acc[2].x += pm * f2.x; acc[2].y += pm * f2.y;
    acc[3].x += pm * f3.x; acc[3].y += pm * f3.y;
}

__global__ __launch_bounds__(256) void agg_heads(int N)
{
    int warp = (blockIdx.x * blockDim.x + threadIdx.x) >> 5;
    int lane = threadIdx.x & 31;
    if (warp >= N) return;

    int e0 = g_rowptr[warp];
    int e1 = g_rowptr[warp + 1];
    int hq = lane & 3;                 // head this lane scores
    int myhead = lane >> 3;            // head this lane accumulates
    float4 s1v = *(const float4*)&g_s1h[warp * 4];
    float s1q = sel4(s1v, hq);

    float lloc = 0.f;
    float2 acc[4];
#pragma unroll
    for (int j = 0; j < 4; j++) acc[j] = make_float2(0.f, 0.f);

    int e = e0;
    int c0 = 0, c1 = 0, c2 = 0, c3 = 0;
    if (e + 4 <= e1) {
        c0 = g_col[e]; c1 = g_col[e + 1]; c2 = g_col[e + 2]; c3 = g_col[e + 3];
    }
    while (e + 4 <= e1) {
        int ne = e + 4;
        int n0 = 0, n1 = 0, n2 = 0, n3 = 0;
        if (ne + 4 <= e1) {                 // prefetch next group's cols
            n0 = g_col[ne]; n1 = g_col[ne + 1]; n2 = g_col[ne + 2]; n3 = g_col[ne + 3];
        }
        float4 s2v0 = *(const float4*)&g_s2h[c0 * 4];
        float4 s2v1 = *(const float4*)&g_s2h[c1 * 4];
        float4 s2v2 = *(const float4*)&g_s2h[c2 * 4];
        float4 s2v3 = *(const float4*)&g_s2h[c3 * 4];
        float4 h0 = ((const float4*)(g_H1h + (size_t)c0 * 128))[lane];
        float4 h1 = ((const float4*)(g_H1h + (size_t)c1 * 128))[lane];
        float4 h2 = ((const float4*)(g_H1h + (size_t)c2 * 128))[lane];
        float4 h3 = ((const float4*)(g_H1h + (size_t)c3 * 128))[lane];

        float s, p0, p1, p2, p3;
        s = s1q + sel4(s2v0, hq); s = -(s > 0.f ? s : ALPHA * s); p0 = __expf(s);
        s = s1q + sel4(s2v1, hq); s = -(s > 0.f ? s : ALPHA * s); p1 = __expf(s);
        s = s1q + sel4(s2v2, hq); s = -(s > 0.f ? s : ALPHA * s); p2 = __expf(s);
        s = s1q + sel4(s2v3, hq); s = -(s > 0.f ? s : ALPHA * s); p3 = __expf(s);
        lloc += p0 + p1 + p2 + p3;
        float pm0 = __shfl_sync(0xffffffffu, p0, myhead, 4);
        float pm1 = __shfl_sync(0xffffffffu, p1, myhead, 4);
        float pm2 = __shfl_sync(0xffffffffu, p2, myhead, 4);
        float pm3 = __shfl_sync(0xffffffffu, p3, myhead, 4);

        acc_f4(acc, pm0, h0);
        acc_f4(acc, pm1, h1);
        acc_f4(acc, pm2, h2);
        acc_f4(acc, pm3, h3);

        e = ne;
        c0 = n0; c1 = n1; c2 = n2; c3 = n3;
    }
    for (; e < e1; e++) {
        int da = g_col[e];
        float4 s2a = *(const float4*)&g_s2h[da * 4];
        float4 ha = ((const float4*)(g_H1h + (size_t)da * 128))[lane];
        float sva = s1q + sel4(s2a, hq);
        float sca = -(sva > 0.f ? sva : ALPHA * sva);
        float pa = __expf(sca);
        lloc += pa;
        float pma = __shfl_sync(0xffffffffu, pa, myhead, 4);
        acc_f4(acc, pma, ha);
    }

    float lh = __shfl_sync(0xffffffffu, lloc, myhead, 4);
    float inv = (e1 > e0) ? 1.f / lh : 0.f;

    float o[8];
#pragma unroll
    for (int j = 0; j < 4; j++) {
        o[2 * j]     = acc[j].x * inv;
        o[2 * j + 1] = acc[j].y * inv;
    }
#pragma unroll
    for (int j = 0; j < 8; j++)
        o[j] = (o[j] > 0.f) ? o[j] : (__expf(o[j]) - 1.f);   // ELU

    __half2 oh[4];
#pragma unroll
    for (int j = 0; j < 4; j++)
        oh[j] = __floats2half2_rn(o[2 * j], o[2 * j + 1]);
    __half2* op = g_hcat16 + (size_t)warp * 128 + myhead * 32 + 4 * (lane & 7);
    op[0] = oh[0]; op[1] = oh[1]; op[2] = oh[2]; op[3] = oh[3];
}

// ---------------------------------------------------------------
// output-layer aggregation (warp per node, dim 64), 4-edge unroll
// ---------------------------------------------------------------
__global__ __launch_bounds__(256) void agg_out(float* __restrict__ out, int N)
{
    int warp = (blockIdx.x * blockDim.x + threadIdx.x) >> 5;
    int lane = threadIdx.x & 31;
    if (warp >= N) return;

    int e0 = g_rowptr[warp];
    int e1 = g_rowptr[warp + 1];
    float s1 = g_s1o[warp];

    float l = 0.f;
    float2 acc = make_float2(0.f, 0.f);

    int e = e0;
    for (; e + 4 <= e1; e += 4) {
        int d0 = g_col[e], d1i = g_col[e + 1], d2i = g_col[e + 2], d3i = g_col[e + 3];
        float t0 = g_s2o[d0], t1 = g_s2o[d1i], t2 = g_s2o[d2i], t3 = g_s2o[d3i];
        float2 v0 = __half22float2(g_H2h[(size_t)d0 * 32 + lane]);
        float2 v1 = __half22float2(g_H2h[(size_t)d1i * 32 + lane]);
        float2 v2 = __half22float2(g_H2h[(size_t)d2i * 32 + lane]);
        float2 v3 = __half22float2(g_H2h[(size_t)d3i * 32 + lane]);

        float s;
        s = s1 + t0; s = -(s > 0.f ? s : ALPHA * s); float p0 = __expf(s);
        s = s1 + t1; s = -(s > 0.f ? s : ALPHA * s); float p1 = __expf(s);
        s = s1 + t2; s = -(s > 0.f ? s : ALPHA * s); float p2 = __expf(s);
        s = s1 + t3; s = -(s > 0.f ? s : ALPHA * s); float p3 = __expf(s);
        l += p0 + p1 + p2 + p3;
        acc.x += p0 * v0.x + p1 * v1.x + p2 * v2.x + p3 * v3.x;
        acc.y += p0 * v0.y + p1 * v1.y + p2 * v2.y + p3 * v3.y;
    }
    for (; e < e1; e++) {
        int da = g_col[e];
        float s2a = g_s2o[da];
        float2 va = __half22float2(g_H2h[(size_t)da * 32 + lane]);
        float s = s1 + s2a;
        s = -(s > 0.f ? s : ALPHA * s);
        float pa = __expf(s);
        l += pa;
        acc.x += pa * va.x;
        acc.y += pa * va.y;
    }

    float va = 0.f, vb = 0.f;
    if (e1 > e0) {
        float inv = 1.f / l;
        va = acc.x * inv;
        vb = acc.y * inv;
    }
    *(float2*)(out + (size_t)warp * 64 + 2 * lane) = make_float2(va, vb);
}

// ---------------------------------------------------------------
extern "C" void kernel_launch(void* const* d_in, const int* in_sizes, int n_in,
                              void* d_out, int out_size)
{
    const float* x          = (const float*)d_in[0];
    const int*   ei_w       = (const int*)d_in[1];
    const float* W_heads    = (const float*)d_in[2];
    const float* attn_heads = (const float*)d_in[3];
    const float* W_out      = (const float*)d_in[4];
    const float* attn_out   = (const float*)d_in[5];
    float* out = (float*)d_out;

    int N = in_sizes[0] / 128;
    int E = in_sizes[1] / 2;

    int nodeWarpBlocks = (N + 7) / 8;
    int edgeBlocks = (E + 255) / 256;
    int scanBlocks = (N + 1023) / 1024;

    // one-time setup (first call is NOT under capture)
    static cudaStream_t sSide = nullptr;
    static cudaEvent_t evFork = nullptr, evJoin = nullptr;
    if (!sSide) {
        cudaStreamCreateWithFlags(&sSide, cudaStreamNonBlocking);
        cudaEventCreateWithFlags(&evFork, cudaEventDisableTiming);
        cudaEventCreateWithFlags(&evJoin, cudaEventDisableTiming);
        cudaFuncSetAttribute(h16_gemm, cudaFuncAttributeMaxDynamicSharedMemorySize, GEMM_SMEM);
    }

    // fork: CSR chain on side stream, GEMM1 on main stream
    cudaEventRecord(evFork, 0);
    cudaStreamWaitEvent(sSide, evFork, 0);

    hist_kernel<<<edgeBlocks, 256, 0, sSide>>>(ei_w, E);     // 1
    scan_p1<<<scanBlocks, 1024, 0, sSide>>>(N);              // 2
    scan_p3<<<scanBlocks, 1024, 0, sSide>>>(scanBlocks, N);  // 3

    // GEMM1 (all 4 heads in-block, fused svec + fp16 mirror) — launch 4 (ncu slot)
    dim3 g1((N + 127) / 128, 1);
    h16_gemm<<<g1, 256, GEMM_SMEM>>>(x, 128, W_heads, attn_heads, 0, N, 128);

    scatter_kernel<<<edgeBlocks, 256, 0, sSide>>>(ei_w, E);  // 5
    cudaEventRecord(evJoin, sSide);

    cudaStreamWaitEvent(0, evJoin, 0);

    // layer-1 softmax+aggregate+ELU -> g_hcat16 (1 warp/node, float4 gather)
    agg_heads<<<nodeWarpBlocks, 256>>>(N);

    // GEMM2 (+ fused svec_out + fp16 mirror)
    dim3 g2((N + 127) / 128, 1);
    h16_gemm<<<g2, 256, GEMM_SMEM>>>(nullptr, 0, W_out, attn_out, 1, N, 256);

    // final aggregation
    agg_out<<<nodeWarpBlocks, 256>>>(out, N);
}